// round 8
// baseline (speedup 1.0000x reference)
#include <cuda_runtime.h>
#include <cuda_bf16.h>
#include <math.h>

#define NB 1024   // batches
#define NN 64     // nodes
#define DD 128    // feature dim
#define EE 1024   // edges
#define HH 4      // heads
#define KK 5
#define LL 2

typedef unsigned long long ull;

// swizzle for h_s / xr_s (GEMM-A operands): conflict-free column reads
#define SWZ(n, d) ((n) * DD + (((d) ^ (((n) & 7) << 2))))

// Edge data sorted by dst (CSR order), built once per launch
__device__ int   g_off[NN + 1];
__device__ int   g_srcp[EE];
__device__ float g_eap[EE];

// W matrices pre-split (3xTF32) and packed in B-fragment order:
// mat m, idx = ((ks*16 + ct)*32 + lane)*2 + j  -> W[ks*8 + lane%4 + j*4][ct*8 + lane/4]
// mats: 0=Wl0 1=Wr0 2=Wl1 3=Wr1 4=W1[0:128] 5=W1[128:256]
__device__ float g_Bhi[6 * 16384];
__device__ float g_Blo[6 * 16384];

__global__ void build_csr_kernel(const int* __restrict__ ei, const float* __restrict__ ea) {
    const int n = threadIdx.x;           // 64 threads
    const int* src = ei;
    const int* dst = ei + EE;
    __shared__ int deg[NN];
    int cnt = 0;
    for (int e = 0; e < EE; ++e) cnt += (dst[e] == n);
    deg[n] = cnt;
    __syncthreads();
    if (n == 0) {
        int s = 0;
        for (int i = 0; i < NN; ++i) { g_off[i] = s; s += deg[i]; }
        g_off[NN] = s;
    }
    __syncthreads();
    int p = g_off[n];
    for (int e = 0; e < EE; ++e) {
        if (dst[e] == n) { g_srcp[p] = src[e]; g_eap[p] = ea[e]; ++p; }
    }
}

__device__ __forceinline__ unsigned tf32r(float v) {
    unsigned r; asm("cvt.rna.tf32.f32 %0, %1;" : "=r"(r) : "f"(v)); return r;
}

__global__ void pack_w_kernel(const float* __restrict__ Wl, const float* __restrict__ Wr,
                              const float* __restrict__ W1) {
    const int m = blockIdx.x;            // 0..5
    const float* src = (m == 0) ? Wl : (m == 1) ? Wr : (m == 2) ? Wl + 16384
                     : (m == 3) ? Wr + 16384 : (m == 4) ? W1 : W1 + 16384;
    for (int idx = threadIdx.x; idx < 16384; idx += blockDim.x) {
        const int j  = idx & 1;
        const int t  = (idx >> 1) & 31;
        const int ct = (idx >> 6) & 15;
        const int ks = idx >> 10;
        const int k = ks * 8 + (t & 3) + j * 4;
        const int n = ct * 8 + (t >> 2);
        const float v = src[k * 128 + n];
        const unsigned hb = tf32r(v);
        const float hf = __uint_as_float(hb);
        g_Bhi[m * 16384 + idx] = hf;
        g_Blo[m * 16384 + idx] = __uint_as_float(tf32r(v - hf));
    }
}

// ---- packed fp32x2 helpers (aggregate phase) ----
__device__ __forceinline__ void fma2(ull& acc, ull a, ull w) {
    asm("fma.rn.f32x2 %0, %1, %2, %0;" : "+l"(acc) : "l"(a), "l"(w));
}
__device__ __forceinline__ ull dup2(float v) {
    ull r;
    asm("mov.b64 %0, {%1, %1};" : "=l"(r) : "r"(__float_as_uint(v)));
    return r;
}

// ---- cp.async helpers ----
__device__ __forceinline__ void cp_async16(unsigned int s, const void* g) {
    asm volatile("cp.async.ca.shared.global [%0], [%1], 16;" :: "r"(s), "l"(g));
}
#define CP_COMMIT() asm volatile("cp.async.commit_group;")
#define CP_WAIT1()  asm volatile("cp.async.wait_group 1;")
#define CP_WAIT0()  asm volatile("cp.async.wait_group 0;")

__device__ __forceinline__ void mma_tf32(float* c, const unsigned* a, unsigned b0, unsigned b1) {
    asm("mma.sync.aligned.m16n8k8.row.col.f32.tf32.tf32.f32 "
        "{%0,%1,%2,%3}, {%4,%5,%6,%7}, {%8,%9}, {%0,%1,%2,%3};"
        : "+f"(c[0]), "+f"(c[1]), "+f"(c[2]), "+f"(c[3])
        : "r"(a[0]), "r"(a[1]), "r"(a[2]), "r"(a[3]), "r"(b0), "r"(b1));
}

// Warp tile: rows [r0, r0+16) x cols [cg*64, (cg+1)*64)  (8 n8-coltiles, c[8][4]).
// A from swizzled smem (fp32, split to tf32 hi/lo on the fly); B streamed through
// double-buffered 2x8KB panel from the packed hi/lo arrays. All 256 threads call.
__device__ __forceinline__ void gemm_mma(float c[8][4], const float* __restrict__ A_s,
                                         const float* __restrict__ Bhi,
                                         const float* __restrict__ Blo,
                                         float* __restrict__ panel,
                                         int tid, int lane, int r0, int cg) {
    const unsigned p0 = (unsigned)__cvta_generic_to_shared(panel);
    const int half = tid >> 7, t = tid & 127;
    const char* srcH = (const char*)(half ? Blo : Bhi);
    cp_async16(p0 + half * 4096 + t * 32,      srcH + t * 32);
    cp_async16(p0 + half * 4096 + t * 32 + 16, srcH + t * 32 + 16);
    CP_COMMIT();
    const int g = lane >> 2, q = lane & 3;
#pragma unroll 1
    for (int ks = 0; ks < 16; ++ks) {
        if (ks < 15) {
            const unsigned pb = p0 + ((ks + 1) & 1) * 8192 + half * 4096 + t * 32;
            const char* gs = srcH + (ks + 1) * 4096 + t * 32;
            cp_async16(pb, gs);
            cp_async16(pb + 16, gs + 16);
            CP_COMMIT();
            CP_WAIT1();
        } else {
            CP_WAIT0();
        }
        __syncthreads();
        const float* P = panel + (ks & 1) * 2048;
        const int kb = ks * 8;
        unsigned ahi[4], alo[4];
        {
            float av[4];
            av[0] = A_s[SWZ(r0 + g,     kb + q)];
            av[1] = A_s[SWZ(r0 + g + 8, kb + q)];
            av[2] = A_s[SWZ(r0 + g,     kb + q + 4)];
            av[3] = A_s[SWZ(r0 + g + 8, kb + q + 4)];
#pragma unroll
            for (int r = 0; r < 4; ++r) {
                ahi[r] = tf32r(av[r]);
                alo[r] = tf32r(av[r] - __uint_as_float(ahi[r]));
            }
        }
#pragma unroll
        for (int i = 0; i < 8; ++i) {
            const int ct = cg * 8 + i;
            const float2 bh = *(const float2*)(P + ct * 64 + lane * 2);
            const float2 bl = *(const float2*)(P + 1024 + ct * 64 + lane * 2);
            const unsigned bh0 = __float_as_uint(bh.x), bh1 = __float_as_uint(bh.y);
            const unsigned bl0 = __float_as_uint(bl.x), bl1 = __float_as_uint(bl.y);
            mma_tf32(c[i], ahi, bh0, bh1);
            mma_tf32(c[i], ahi, bl0, bl1);
            mma_tf32(c[i], alo, bh0, bh1);
        }
        __syncthreads();
    }
}

__device__ __forceinline__ void cinit(float c[8][4], const float* __restrict__ bias,
                                      int cg, int lane) {
#pragma unroll
    for (int i = 0; i < 8; ++i) {
        const float2 bv = *(const float2*)(bias + (cg * 8 + i) * 8 + (lane & 3) * 2);
        c[i][0] = bv.x; c[i][1] = bv.y; c[i][2] = bv.x; c[i][3] = bv.y;
    }
}

__device__ __forceinline__ void cstore_plain(const float c[8][4], float* __restrict__ dst,
                                             int r0, int cg, int lane) {
    const int g = lane >> 2, q = lane & 3;
#pragma unroll
    for (int i = 0; i < 8; ++i) {
        const int col = (cg * 8 + i) * 8 + q * 2;
        *(float2*)(dst + (r0 + g) * DD + col)     = make_float2(c[i][0], c[i][1]);
        *(float2*)(dst + (r0 + g + 8) * DD + col) = make_float2(c[i][2], c[i][3]);
    }
}

__device__ __forceinline__ void cstore_swz(const float c[8][4], float* __restrict__ dst,
                                           int r0, int cg, int lane) {
    const int g = lane >> 2, q = lane & 3;
#pragma unroll
    for (int i = 0; i < 8; ++i) {
        const int col = (cg * 8 + i) * 8 + q * 2;
        *(float2*)(dst + SWZ(r0 + g, col))     = make_float2(c[i][0], c[i][1]);
        *(float2*)(dst + SWZ(r0 + g + 8, col)) = make_float2(c[i][2], c[i][3]);
    }
}

__device__ __forceinline__ void cstore_relu(const float c[8][4], float* __restrict__ dst,
                                            int r0, int cg, int lane) {
    const int g = lane >> 2, q = lane & 3;
#pragma unroll
    for (int i = 0; i < 8; ++i) {
        const int col = (cg * 8 + i) * 8 + q * 2;
        *(float2*)(dst + (r0 + g) * DD + col) =
            make_float2(fmaxf(c[i][0], 0.f), fmaxf(c[i][1], 0.f));
        *(float2*)(dst + (r0 + g + 8) * DD + col) =
            make_float2(fmaxf(c[i][2], 0.f), fmaxf(c[i][3], 0.f));
    }
}

__global__ __launch_bounds__(256, 2) void gat_kernel(
    const int* __restrict__ x,
    const float* __restrict__ attr_emb, const float* __restrict__ opt_emb,
    const float* __restrict__ prior,
    const float* __restrict__ We, const float* __restrict__ att,
    const float* __restrict__ bl, const float* __restrict__ br,
    const float* __restrict__ conv_bias, const float* __restrict__ ln_g,
    const float* __restrict__ ln_b,
    const float* __restrict__ b1,
    const float* __restrict__ W2, const float* __restrict__ b2,
    float* __restrict__ out) {
    extern __shared__ float sm[];
    float* h_s   = sm;                     // 8192 floats, SWZ layout (h; starts as T0)
    float* xl_s  = h_s + NN * DD;          // 8192, plain layout
    float* xr_s  = xl_s + NN * DD;         // 8192, SWZ layout (xr; later T0)
    float* un_s  = xr_s + NN * DD;         // 4096: union{ W panel | alpha[H][EE] | epilogue }
    unsigned char* esrc_s = (unsigned char*)(un_s + HH * EE);  // 1024 B

    const int b = blockIdx.x;
    const int tid = threadIdx.x;
    const int lane = tid & 31;
    const int w = tid >> 5;                // 0..7

    const int g_r0 = (w & 3) * 16;         // GEMM rowtile
    const int g_cg = w >> 2;               // GEMM colgroup (0..1)

    // ---- load packed src indices ----
    for (int e = tid; e < EE; e += 256) esrc_s[e] = (unsigned char)g_srcp[e];

    // ---- h = T0 = (attr_emb + opt_emb[n, x]) * prior ----
    for (int idx = tid; idx < NN * DD; idx += 256) {
        const int n = idx >> 7, d = idx & 127;
        const int xv = x[b * NN + n];
        h_s[SWZ(n, d)] = (attr_emb[idx] + opt_emb[(n * KK + xv) * DD + d]) * prior[n];
    }
    __syncthreads();

    for (int l = 0; l < LL; ++l) {
        // ---- xl = h@Wl + bl ; xr = h@Wr + br  (tensor-core 3xTF32) ----
        {
            float c[8][4];
            cinit(c, bl + l * DD, g_cg, lane);
            gemm_mma(c, h_s, g_Bhi + (2 * l) * 16384, g_Blo + (2 * l) * 16384,
                     un_s, tid, lane, g_r0, g_cg);
            cstore_plain(c, xl_s, g_r0, g_cg, lane);

            cinit(c, br + l * DD, g_cg, lane);
            gemm_mma(c, h_s, g_Bhi + (2 * l + 1) * 16384, g_Blo + (2 * l + 1) * 16384,
                     un_s, tid, lane, g_r0, g_cg);
            cstore_swz(c, xr_s, g_r0, g_cg, lane);
        }
        __syncthreads();

        float* alpha_s = un_s;             // [H][EE]

        // ---- alpha: warp per destination node ----
        {
            const int head = lane >> 3;
            const float4 We4  = *(const float4*)(We  + l * DD + lane * 4);
            const float4 att4 = *(const float4*)(att + l * DD + lane * 4);
            for (int n = w; n < NN; n += 8) {
                const float4 xr4 = *(const float4*)(xr_s + SWZ(n, lane * 4));
                const int e0 = g_off[n], e1 = g_off[n + 1];
#pragma unroll 2
                for (int i = e0; i < e1; ++i) {
                    const int s = esrc_s[i];
                    const float eav = g_eap[i];
                    const float4 xl4 = *(const float4*)(xl_s + s * DD + lane * 4);
                    float z0 = xl4.x + xr4.x + eav * We4.x;
                    float z1 = xl4.y + xr4.y + eav * We4.y;
                    float z2 = xl4.z + xr4.z + eav * We4.z;
                    float z3 = xl4.w + xr4.w + eav * We4.w;
                    z0 = z0 > 0.f ? z0 : 0.2f * z0;
                    z1 = z1 > 0.f ? z1 : 0.2f * z1;
                    z2 = z2 > 0.f ? z2 : 0.2f * z2;
                    z3 = z3 > 0.f ? z3 : 0.2f * z3;
                    float p = z0 * att4.x + z1 * att4.y + z2 * att4.z + z3 * att4.w;
                    p += __shfl_xor_sync(0xffffffffu, p, 1);
                    p += __shfl_xor_sync(0xffffffffu, p, 2);
                    p += __shfl_xor_sync(0xffffffffu, p, 4);
                    if ((lane & 7) == 0) alpha_s[head * EE + i] = p;
                }
            }
        }
        __syncthreads();

        // ---- softmax per node: warp-parallel, lanes = (8 edges) x (4 heads) ----
        {
            const int head = lane >> 3;
            const int el   = lane & 7;
            float* a = alpha_s + head * EE;
            for (int n = w; n < NN; n += 8) {
                const int e0 = g_off[n], e1 = g_off[n + 1];
                float m = -INFINITY;
                for (int i = e0 + el; i < e1; i += 8) m = fmaxf(m, a[i]);
                m = fmaxf(m, __shfl_xor_sync(0xffffffffu, m, 1));
                m = fmaxf(m, __shfl_xor_sync(0xffffffffu, m, 2));
                m = fmaxf(m, __shfl_xor_sync(0xffffffffu, m, 4));
                float s = 0.f;
                for (int i = e0 + el; i < e1; i += 8) {
                    const float ex = __expf(a[i] - m);
                    a[i] = ex;
                    s += ex;
                }
                s += __shfl_xor_sync(0xffffffffu, s, 1);
                s += __shfl_xor_sync(0xffffffffu, s, 2);
                s += __shfl_xor_sync(0xffffffffu, s, 4);
                const float inv = 1.f / s;
                for (int i = e0 + el; i < e1; i += 8) a[i] *= inv;
            }
        }
        __syncthreads();

        // ---- aggregate (f32x2): out[n,d] = sum_in xl[src,d]*a  (into xr_s, SWZ) ----
        {
            const int dp = tid & 63;       // d-pair -> d = dp*2
            const int q = tid >> 6;        // 0..3
            const float* a = alpha_s + (dp >> 4) * EE;
            for (int n = q; n < NN; n += 4) {
                ull acc = 0ull;
                const int e0 = g_off[n], e1 = g_off[n + 1];
#pragma unroll 4
                for (int i = e0; i < e1; ++i) {
                    const ull xv = *(const ull*)(xl_s + (int)esrc_s[i] * DD + dp * 2);
                    fma2(acc, xv, dup2(a[i]));
                }
                *(ull*)(xr_s + SWZ(n, dp * 2)) = acc;
            }
        }
        __syncthreads();

        // ---- g = LN(out + conv_bias); h += elu(g)   (warp per node) ----
        for (int n = w; n < NN; n += 8) {
            const float4 gv = *(const float4*)(xr_s + SWZ(n, lane * 4));
            float v[4];
            v[0] = gv.x + conv_bias[l * DD + lane * 4 + 0];
            v[1] = gv.y + conv_bias[l * DD + lane * 4 + 1];
            v[2] = gv.z + conv_bias[l * DD + lane * 4 + 2];
            v[3] = gv.w + conv_bias[l * DD + lane * 4 + 3];
            float sum = v[0] + v[1] + v[2] + v[3];
            float sq  = v[0]*v[0] + v[1]*v[1] + v[2]*v[2] + v[3]*v[3];
#pragma unroll
            for (int o = 16; o; o >>= 1) {
                sum += __shfl_xor_sync(0xffffffffu, sum, o);
                sq  += __shfl_xor_sync(0xffffffffu, sq, o);
            }
            const float mu = sum * (1.f / DD);
            const float var = sq * (1.f / DD) - mu * mu;
            const float rstd = rsqrtf(var + 1e-5f);
            const int hb = SWZ(n, lane * 4);
#pragma unroll
            for (int i = 0; i < 4; ++i) {
                const int d = lane * 4 + i;
                float t = (v[i] - mu) * rstd * ln_g[l * DD + d] + ln_b[l * DD + d];
                t = t > 0.f ? t : expm1f(t);
                h_s[hb + i] += t;
            }
        }
        __syncthreads();
    }

    // ---- recompute T0 into xr_s (SWZ) ----
    for (int idx = tid; idx < NN * DD; idx += 256) {
        const int n = idx >> 7, d = idx & 127;
        const int xv = x[b * NN + n];
        xr_s[SWZ(n, d)] = (attr_emb[idx] + opt_emb[(n * KK + xv) * DD + d]) * prior[n];
    }
    __syncthreads();

    // ---- MLP: q = relu([T0, h] @ W1 + b1) -> xl_s ----
    {
        float c[8][4];
        cinit(c, b1, g_cg, lane);
        gemm_mma(c, xr_s, g_Bhi + 4 * 16384, g_Blo + 4 * 16384, un_s, tid, lane, g_r0, g_cg);
        gemm_mma(c, h_s,  g_Bhi + 5 * 16384, g_Blo + 5 * 16384, un_s, tid, lane, g_r0, g_cg);
        cstore_relu(c, xl_s, g_r0, g_cg, lane);
    }
    __syncthreads();

    float* rel_s = un_s;          // [0..63], relsum at [64], partials at [128..384)

    // ---- rel[n] = sigmoid(q[n].W2 + b2)   (warp per node) ----
    {
        const long long OR = (long long)NB * DD;
        const float4 w24 = *(const float4*)(W2 + lane * 4);
        for (int n = w; n < NN; n += 8) {
            const float4 qv = *(const float4*)(xl_s + n * DD + lane * 4);
            float p = qv.x * w24.x + qv.y * w24.y + qv.z * w24.z + qv.w * w24.w;
#pragma unroll
            for (int o = 16; o; o >>= 1) p += __shfl_xor_sync(0xffffffffu, p, o);
            if (lane == 0) {
                const float r = 1.f / (1.f + expf(-(p + b2[0])));
                rel_s[n] = r;
                out[OR + (long long)b * NN + n] = r;
            }
        }
    }
    __syncthreads();

    // ---- rel sum (warp 0) ----
    if (w == 0) {
        float v = rel_s[lane] + rel_s[lane + 32];
#pragma unroll
        for (int o = 16; o; o >>= 1) v += __shfl_xor_sync(0xffffffffu, v, o);
        if (lane == 0) rel_s[64] = v;
    }

    // ---- f_scale partials ----
    {
        const int d = tid & 127;
        const int q = tid >> 7;            // 0..1
        float acc = 0.f;
        for (int n = q; n < NN; n += 2)
            acc = fmaf(h_s[SWZ(n, d)], rel_s[n], acc);
        un_s[128 + q * DD + d] = acc;
    }

    // ---- hat_T output: [T0(=xr_s), h] ----
    {
        const long long OH = (long long)NB * DD + (long long)NB * NN;
        for (int idx = tid; idx < NN * DD; idx += 256) {
            const int n = idx >> 7, d = idx & 127;
            const long long base = OH + ((long long)b * NN + n) * (2 * DD);
            out[base + d] = xr_s[SWZ(n, d)];
            out[base + DD + d] = h_s[SWZ(n, d)];
        }
    }
    __syncthreads();

    if (tid < DD) {
        const float num = un_s[128 + tid] + un_s[256 + tid];
        out[(long long)b * DD + tid] = num / (rel_s[64] + 1e-8f);
    }
}

extern "C" void kernel_launch(void* const* d_in, const int* in_sizes, int n_in,
                              void* d_out, int out_size) {
    const int*   x         = (const int*)d_in[0];
    const int*   ei        = (const int*)d_in[1];
    const float* ea        = (const float*)d_in[2];
    const float* attr_emb  = (const float*)d_in[3];
    const float* opt_emb   = (const float*)d_in[4];
    const float* prior     = (const float*)d_in[5];
    const float* Wl        = (const float*)d_in[6];
    const float* bl        = (const float*)d_in[7];
    const float* Wr        = (const float*)d_in[8];
    const float* br        = (const float*)d_in[9];
    const float* We        = (const float*)d_in[10];
    const float* att       = (const float*)d_in[11];
    const float* conv_bias = (const float*)d_in[12];
    const float* ln_g      = (const float*)d_in[13];
    const float* ln_b      = (const float*)d_in[14];
    const float* W1        = (const float*)d_in[15];
    const float* b1        = (const float*)d_in[16];
    const float* W2        = (const float*)d_in[17];
    const float* b2        = (const float*)d_in[18];
    float* out = (float*)d_out;

    const size_t smem = 3 * NN * DD * sizeof(float) + HH * EE * sizeof(float) + EE;
    cudaFuncSetAttribute(gat_kernel, cudaFuncAttributeMaxDynamicSharedMemorySize, (int)smem);

    build_csr_kernel<<<1, 64>>>(ei, ea);
    pack_w_kernel<<<6, 256>>>(Wl, Wr, W1);
    gat_kernel<<<NB, 256, smem>>>(x, attr_emb, opt_emb, prior,
                                  We, att, bl, br, conv_bias,
                                  ln_g, ln_b, b1, W2, b2, out);
}

// round 9
// speedup vs baseline: 1.6722x; 1.6722x over previous
#include <cuda_runtime.h>
#include <cuda_bf16.h>
#include <math.h>

#define NB 1024   // batches
#define NN 64     // nodes
#define DD 128    // feature dim
#define EE 1024   // edges
#define HH 4      // heads
#define KK 5
#define LL 2

typedef unsigned long long ull;

// Edge data sorted by dst (CSR order), built once per launch
__device__ int   g_off[NN + 1];
__device__ int   g_srcp[EE];
__device__ float g_eap[EE];

// Fast CSR build: one thread per edge, stable (edge-order-preserving) bucket sort.
__global__ __launch_bounds__(EE) void build_csr_fast(const int* __restrict__ ei,
                                                     const float* __restrict__ ea) {
    __shared__ int dstS[EE];
    __shared__ int degS[NN];
    __shared__ int offS[NN + 1];
    const int e = threadIdx.x;             // 0..1023
    if (e < NN) degS[e] = 0;
    __syncthreads();
    const int d = ei[EE + e];
    dstS[e] = d;
    atomicAdd(&degS[d], 1);
    __syncthreads();
    if (e == 0) {
        int s = 0;
        for (int i = 0; i < NN; ++i) { offS[i] = s; s += degS[i]; }
        offS[NN] = s;
    }
    __syncthreads();
    // stable rank: edges before e with the same dst
    int rank = 0;
    for (int j = 0; j < e; ++j) rank += (dstS[j] == d);
    const int p = offS[d] + rank;
    g_srcp[p] = ei[e];
    g_eap[p]  = ea[e];
    if (e <= NN) g_off[e] = offS[e];
}

// ---- packed fp32x2 helpers (B300 FFMA2) ----
__device__ __forceinline__ void fma2(ull& acc, ull a, ull w) {
    asm("fma.rn.f32x2 %0, %1, %2, %0;" : "+l"(acc) : "l"(a), "l"(w));
}
__device__ __forceinline__ ull dup2(float v) {
    ull r;
    asm("mov.b64 %0, {%1, %1};" : "=l"(r) : "r"(__float_as_uint(v)));
    return r;
}
__device__ __forceinline__ void unpack2(ull v, float& lo, float& hi) {
    asm("mov.b64 {%0, %1}, %2;" : "=f"(lo), "=f"(hi) : "l"(v));
}

// ---- cp.async helpers ----
__device__ __forceinline__ void cp_async16(unsigned int s, const void* g) {
    asm volatile("cp.async.ca.shared.global [%0], [%1], 16;" :: "r"(s), "l"(g));
}
#define CP_COMMIT() asm volatile("cp.async.commit_group;")
#define CP_WAIT1()  asm volatile("cp.async.wait_group 1;")
#define CP_WAIT0()  asm volatile("cp.async.wait_group 0;")

struct Acc84 { ull v[8][2]; };

__device__ __forceinline__ void acc_init_bias(Acc84& acc, const float* __restrict__ bias,
                                              int col0) {
    const ulonglong2 bv = *(const ulonglong2*)(bias + col0);
#pragma unroll
    for (int r = 0; r < 8; ++r) { acc.v[r][0] = bv.x; acc.v[r][1] = bv.y; }
}

// acc += A[row0..row0+8][:] @ W[:,col0..col0+4], K=128, W staged through smem panels
// panel: 2 x 2048 floats (2 x 8KB) in the union region
__device__ __forceinline__ void gemm_accum(Acc84& acc, const float* __restrict__ A,
                                           const float* __restrict__ Wg,
                                           float* __restrict__ panel,
                                           int row0, int col0, int tid) {
    const unsigned int p0 = (unsigned int)__cvta_generic_to_shared(panel);
    const char* wsrc = (const char*)Wg;
    cp_async16(p0 + tid * 32,      wsrc + tid * 32);
    cp_async16(p0 + tid * 32 + 16, wsrc + tid * 32 + 16);
    CP_COMMIT();
#pragma unroll 1
    for (int c = 0; c < 8; ++c) {
        if (c < 7) {
            const unsigned int pb = p0 + ((c + 1) & 1) * 8192;
            const char* g = wsrc + (c + 1) * 8192;
            cp_async16(pb + tid * 32,      g + tid * 32);
            cp_async16(pb + tid * 32 + 16, g + tid * 32 + 16);
            CP_COMMIT();
            CP_WAIT1();
        } else {
            CP_WAIT0();
        }
        __syncthreads();
        const float* P = panel + (c & 1) * 2048;
#pragma unroll
        for (int k4 = 0; k4 < 4; ++k4) {
            const int kb = c * 16 + k4 * 4;
            float4 a[8];
#pragma unroll
            for (int r = 0; r < 8; ++r) a[r] = *(const float4*)(A + (row0 + r) * DD + kb);
#pragma unroll
            for (int kk = 0; kk < 4; ++kk) {
                const ulonglong2 wv = *(const ulonglong2*)(P + (k4 * 4 + kk) * DD + col0);
#pragma unroll
                for (int r = 0; r < 8; ++r) {
                    const float av = (kk == 0) ? a[r].x : (kk == 1) ? a[r].y
                                   : (kk == 2) ? a[r].z : a[r].w;
                    const ull ad = dup2(av);
                    fma2(acc.v[r][0], ad, wv.x);
                    fma2(acc.v[r][1], ad, wv.y);
                }
            }
        }
        __syncthreads();
    }
}

__device__ __forceinline__ void acc_store(const Acc84& acc, float* __restrict__ dstS,
                                          int row0, int col0) {
#pragma unroll
    for (int r = 0; r < 8; ++r) {
        ulonglong2 o; o.x = acc.v[r][0]; o.y = acc.v[r][1];
        *(ulonglong2*)(dstS + (row0 + r) * DD + col0) = o;
    }
}

__global__ __launch_bounds__(256, 2) void gat_kernel(
    const int* __restrict__ x,
    const float* __restrict__ attr_emb, const float* __restrict__ opt_emb,
    const float* __restrict__ prior,
    const float* __restrict__ Wl, const float* __restrict__ bl,
    const float* __restrict__ Wr, const float* __restrict__ br,
    const float* __restrict__ We, const float* __restrict__ att,
    const float* __restrict__ conv_bias, const float* __restrict__ ln_g,
    const float* __restrict__ ln_b,
    const float* __restrict__ W1, const float* __restrict__ b1,
    const float* __restrict__ W2, const float* __restrict__ b2,
    float* __restrict__ out) {
    extern __shared__ float sm[];
    float* h_s   = sm;                     // 8192 floats (h; starts as T0)
    float* xl_s  = h_s + NN * DD;          // 8192
    float* xr_s  = xl_s + NN * DD;         // 8192 (aggregate out; later T0 recomputed)
    float* un_s  = xr_s + NN * DD;         // 4096: union{ W panels | alpha[H][EE] | epilogue }
    unsigned char* esrc_s = (unsigned char*)(un_s + HH * EE);  // 1024 B

    const int b = blockIdx.x;
    const int tid = threadIdx.x;
    const int lane = tid & 31;
    const int w = tid >> 5;                // 0..7

    const int g_row0 = w * 8;
    const int g_col0 = lane * 4;

    // ---- load packed src indices ----
    for (int e = tid; e < EE; e += 256) esrc_s[e] = (unsigned char)g_srcp[e];

    // ---- h = T0 = (attr_emb + opt_emb[n, x]) * prior ----
    for (int idx = tid; idx < NN * DD; idx += 256) {
        const int n = idx >> 7, d = idx & 127;
        const int xv = x[b * NN + n];
        h_s[idx] = (attr_emb[idx] + opt_emb[(n * KK + xv) * DD + d]) * prior[n];
    }
    __syncthreads();

    for (int l = 0; l < LL; ++l) {
        // ---- xl = h@Wl + bl ; xr = h@Wr + br ----
        {
            Acc84 acc;
            acc_init_bias(acc, bl + l * DD, g_col0);
            gemm_accum(acc, h_s, Wl + l * DD * DD, un_s, g_row0, g_col0, tid);
            acc_store(acc, xl_s, g_row0, g_col0);

            acc_init_bias(acc, br + l * DD, g_col0);
            gemm_accum(acc, h_s, Wr + l * DD * DD, un_s, g_row0, g_col0, tid);
            acc_store(acc, xr_s, g_row0, g_col0);
        }
        __syncthreads();

        float* alpha_s = un_s;             // [H][EE]

        // ---- alpha: warp per destination node ----
        {
            const int head = lane >> 3;
            const float4 We4  = *(const float4*)(We  + l * DD + lane * 4);
            const float4 att4 = *(const float4*)(att + l * DD + lane * 4);
            for (int n = w; n < NN; n += 8) {
                const float4 xr4 = *(const float4*)(xr_s + n * DD + lane * 4);
                const int e0 = g_off[n], e1 = g_off[n + 1];
#pragma unroll 2
                for (int i = e0; i < e1; ++i) {
                    const int s = esrc_s[i];
                    const float eav = g_eap[i];
                    const float4 xl4 = *(const float4*)(xl_s + s * DD + lane * 4);
                    float z0 = xl4.x + xr4.x + eav * We4.x;
                    float z1 = xl4.y + xr4.y + eav * We4.y;
                    float z2 = xl4.z + xr4.z + eav * We4.z;
                    float z3 = xl4.w + xr4.w + eav * We4.w;
                    z0 = z0 > 0.f ? z0 : 0.2f * z0;
                    z1 = z1 > 0.f ? z1 : 0.2f * z1;
                    z2 = z2 > 0.f ? z2 : 0.2f * z2;
                    z3 = z3 > 0.f ? z3 : 0.2f * z3;
                    float p = z0 * att4.x + z1 * att4.y + z2 * att4.z + z3 * att4.w;
                    p += __shfl_xor_sync(0xffffffffu, p, 1);
                    p += __shfl_xor_sync(0xffffffffu, p, 2);
                    p += __shfl_xor_sync(0xffffffffu, p, 4);
                    if ((lane & 7) == 0) alpha_s[head * EE + i] = p;
                }
            }
        }
        __syncthreads();

        // ---- softmax per node: warp-parallel, lanes = (8 edges) x (4 heads) ----
        {
            const int head = lane >> 3;
            const int el   = lane & 7;
            float* a = alpha_s + head * EE;
            for (int n = w; n < NN; n += 8) {
                const int e0 = g_off[n], e1 = g_off[n + 1];
                float m = -INFINITY;
                for (int i = e0 + el; i < e1; i += 8) m = fmaxf(m, a[i]);
                m = fmaxf(m, __shfl_xor_sync(0xffffffffu, m, 1));
                m = fmaxf(m, __shfl_xor_sync(0xffffffffu, m, 2));
                m = fmaxf(m, __shfl_xor_sync(0xffffffffu, m, 4));
                float s = 0.f;
                for (int i = e0 + el; i < e1; i += 8) {
                    const float ex = __expf(a[i] - m);
                    a[i] = ex;
                    s += ex;
                }
                s += __shfl_xor_sync(0xffffffffu, s, 1);
                s += __shfl_xor_sync(0xffffffffu, s, 2);
                s += __shfl_xor_sync(0xffffffffu, s, 4);
                const float inv = 1.f / s;
                for (int i = e0 + el; i < e1; i += 8) a[i] *= inv;
            }
        }
        __syncthreads();

        // ---- aggregate (f32x2): out[n,d] = sum_in xl[src,d]*a  (into xr_s) ----
        {
            const int dp = tid & 63;       // d-pair -> d = dp*2
            const int q = tid >> 6;        // 0..3
            const float* a = alpha_s + (dp >> 4) * EE;
            for (int n = q; n < NN; n += 4) {
                ull acc = 0ull;
                const int e0 = g_off[n], e1 = g_off[n + 1];
#pragma unroll 4
                for (int i = e0; i < e1; ++i) {
                    const ull xv = *(const ull*)(xl_s + (int)esrc_s[i] * DD + dp * 2);
                    fma2(acc, xv, dup2(a[i]));
                }
                *(ull*)(xr_s + n * DD + dp * 2) = acc;
            }
        }
        __syncthreads();

        // ---- g = LN(out + conv_bias); h += elu(g)   (warp per node) ----
        for (int n = w; n < NN; n += 8) {
            const float4 gv = *(const float4*)(xr_s + n * DD + lane * 4);
            float v[4];
            v[0] = gv.x + conv_bias[l * DD + lane * 4 + 0];
            v[1] = gv.y + conv_bias[l * DD + lane * 4 + 1];
            v[2] = gv.z + conv_bias[l * DD + lane * 4 + 2];
            v[3] = gv.w + conv_bias[l * DD + lane * 4 + 3];
            float sum = v[0] + v[1] + v[2] + v[3];
            float sq  = v[0]*v[0] + v[1]*v[1] + v[2]*v[2] + v[3]*v[3];
#pragma unroll
            for (int o = 16; o; o >>= 1) {
                sum += __shfl_xor_sync(0xffffffffu, sum, o);
                sq  += __shfl_xor_sync(0xffffffffu, sq, o);
            }
            const float mu = sum * (1.f / DD);
            const float var = sq * (1.f / DD) - mu * mu;
            const float rstd = rsqrtf(var + 1e-5f);
#pragma unroll
            for (int i = 0; i < 4; ++i) {
                const int d = lane * 4 + i;
                float t = (v[i] - mu) * rstd * ln_g[l * DD + d] + ln_b[l * DD + d];
                t = t > 0.f ? t : expm1f(t);
                h_s[n * DD + d] += t;
            }
        }
        __syncthreads();
    }

    // ---- recompute T0 into xr_s ----
    for (int idx = tid; idx < NN * DD; idx += 256) {
        const int n = idx >> 7, d = idx & 127;
        const int xv = x[b * NN + n];
        xr_s[idx] = (attr_emb[idx] + opt_emb[(n * KK + xv) * DD + d]) * prior[n];
    }
    __syncthreads();

    // ---- MLP: q = relu([T0, h] @ W1 + b1) -> xl_s ----
    {
        Acc84 acc;
        acc_init_bias(acc, b1, g_col0);
        gemm_accum(acc, xr_s, W1, un_s, g_row0, g_col0, tid);
        gemm_accum(acc, h_s, W1 + DD * DD, un_s, g_row0, g_col0, tid);
#pragma unroll
        for (int r = 0; r < 8; ++r) {
            float v0, v1, v2, v3;
            unpack2(acc.v[r][0], v0, v1);
            unpack2(acc.v[r][1], v2, v3);
            float* d = xl_s + (g_row0 + r) * DD + g_col0;
            d[0] = fmaxf(v0, 0.f);
            d[1] = fmaxf(v1, 0.f);
            d[2] = fmaxf(v2, 0.f);
            d[3] = fmaxf(v3, 0.f);
        }
    }
    __syncthreads();

    float* rel_s = un_s;          // [0..63], relsum at [64], partials at [128..384)

    // ---- rel[n] = sigmoid(q[n].W2 + b2)   (warp per node) ----
    {
        const long long OR = (long long)NB * DD;
        const float4 w24 = *(const float4*)(W2 + lane * 4);
        for (int n = w; n < NN; n += 8) {
            const float4 qv = *(const float4*)(xl_s + n * DD + lane * 4);
            float p = qv.x * w24.x + qv.y * w24.y + qv.z * w24.z + qv.w * w24.w;
#pragma unroll
            for (int o = 16; o; o >>= 1) p += __shfl_xor_sync(0xffffffffu, p, o);
            if (lane == 0) {
                const float r = 1.f / (1.f + expf(-(p + b2[0])));
                rel_s[n] = r;
                out[OR + (long long)b * NN + n] = r;
            }
        }
    }
    __syncthreads();

    // ---- rel sum (warp 0) ----
    if (w == 0) {
        float v = rel_s[lane] + rel_s[lane + 32];
#pragma unroll
        for (int o = 16; o; o >>= 1) v += __shfl_xor_sync(0xffffffffu, v, o);
        if (lane == 0) rel_s[64] = v;
    }

    // ---- f_scale partials ----
    {
        const int d = tid & 127;
        const int q = tid >> 7;            // 0..1
        float acc = 0.f;
        for (int n = q; n < NN; n += 2)
            acc = fmaf(h_s[n * DD + d], rel_s[n], acc);
        un_s[128 + q * DD + d] = acc;
    }

    // ---- hat_T output: [T0(=xr_s), h] ----
    {
        const long long OH = (long long)NB * DD + (long long)NB * NN;
        for (int idx = tid; idx < NN * DD; idx += 256) {
            const int n = idx >> 7, d = idx & 127;
            const long long base = OH + ((long long)b * NN + n) * (2 * DD);
            out[base + d] = xr_s[idx];
            out[base + DD + d] = h_s[idx];
        }
    }
    __syncthreads();

    if (tid < DD) {
        const float num = un_s[128 + tid] + un_s[256 + tid];
        out[(long long)b * DD + tid] = num / (rel_s[64] + 1e-8f);
    }
}

extern "C" void kernel_launch(void* const* d_in, const int* in_sizes, int n_in,
                              void* d_out, int out_size) {
    const int*   x         = (const int*)d_in[0];
    const int*   ei        = (const int*)d_in[1];
    const float* ea        = (const float*)d_in[2];
    const float* attr_emb  = (const float*)d_in[3];
    const float* opt_emb   = (const float*)d_in[4];
    const float* prior     = (const float*)d_in[5];
    const float* Wl        = (const float*)d_in[6];
    const float* bl        = (const float*)d_in[7];
    const float* Wr        = (const float*)d_in[8];
    const float* br        = (const float*)d_in[9];
    const float* We        = (const float*)d_in[10];
    const float* att       = (const float*)d_in[11];
    const float* conv_bias = (const float*)d_in[12];
    const float* ln_g      = (const float*)d_in[13];
    const float* ln_b      = (const float*)d_in[14];
    const float* W1        = (const float*)d_in[15];
    const float* b1        = (const float*)d_in[16];
    const float* W2        = (const float*)d_in[17];
    const float* b2        = (const float*)d_in[18];
    float* out = (float*)d_out;

    const size_t smem = 3 * NN * DD * sizeof(float) + HH * EE * sizeof(float) + EE;
    cudaFuncSetAttribute(gat_kernel, cudaFuncAttributeMaxDynamicSharedMemorySize, (int)smem);

    build_csr_fast<<<1, EE>>>(ei, ea);
    gat_kernel<<<NB, 256, smem>>>(x, attr_emb, opt_emb, prior,
                                  Wl, bl, Wr, br, We, att, conv_bias,
                                  ln_g, ln_b, W1, b1, W2, b2, out);
}

// round 10
// speedup vs baseline: 1.9114x; 1.1430x over previous
#include <cuda_runtime.h>
#include <cuda_bf16.h>
#include <cuda_fp16.h>
#include <math.h>

#define NB 1024   // batches
#define NN 64     // nodes
#define DD 128    // feature dim
#define EE 1024   // edges
#define HH 4      // heads
#define KK 5
#define LL 2

typedef unsigned long long ull;

// Edge data sorted by dst (CSR order), built once per launch
__device__ int   g_off[NN + 1];
__device__ int   g_srcp[EE];
__device__ float g_eap[EE];

// W matrices as fp16 hi/lo, packed in m16n8k16 B-fragment order:
// mat m: slot s = (ks*16 + ct)*32 + lane; u32[4] = {bhi0, bhi1, blo0, blo1}
//   bhi0 = {hi(W[k0][n]), hi(W[k0+1][n])}, bhi1 = {hi(W[k0+8][n]), hi(W[k0+9][n])}
//   k0 = ks*16 + (lane&3)*2, n = ct*8 + (lane>>2)
// mats: 0=Wl0 1=Wr0 2=Wl1 3=Wr1 4=W1[0:128] 5=W1[128:256]
__device__ unsigned g_Bpack[6 * 16384];

// Fast CSR build: one thread per edge, stable (edge-order-preserving) bucket sort.
__global__ __launch_bounds__(EE) void build_csr_fast(const int* __restrict__ ei,
                                                     const float* __restrict__ ea) {
    __shared__ int dstS[EE];
    __shared__ int degS[NN];
    __shared__ int offS[NN + 1];
    const int e = threadIdx.x;             // 0..1023
    if (e < NN) degS[e] = 0;
    __syncthreads();
    const int d = ei[EE + e];
    dstS[e] = d;
    atomicAdd(&degS[d], 1);
    __syncthreads();
    if (e == 0) {
        int s = 0;
        for (int i = 0; i < NN; ++i) { offS[i] = s; s += degS[i]; }
        offS[NN] = s;
    }
    __syncthreads();
    int rank = 0;
    for (int j = 0; j < e; ++j) rank += (dstS[j] == d);
    const int p = offS[d] + rank;
    g_srcp[p] = ei[e];
    g_eap[p]  = ea[e];
    if (e <= NN) g_off[e] = offS[e];
}

__device__ __forceinline__ unsigned packh2(__half a, __half b) {
    __half2 h; h.x = a; h.y = b;
    return *(const unsigned*)&h;
}

__global__ void pack_w_kernel(const float* __restrict__ Wl, const float* __restrict__ Wr,
                              const float* __restrict__ W1) {
    const int m = blockIdx.x;            // 0..5
    const float* src = (m == 0) ? Wl : (m == 1) ? Wr : (m == 2) ? Wl + 16384
                     : (m == 3) ? Wr + 16384 : (m == 4) ? W1 : W1 + 16384;
    for (int s = threadIdx.x; s < 4096; s += blockDim.x) {
        const int lane = s & 31, ct = (s >> 5) & 15, ks = s >> 9;
        const int n  = ct * 8 + (lane >> 2);
        const int k0 = ks * 16 + (lane & 3) * 2;
        float v[4];
        v[0] = src[(k0)     * DD + n];
        v[1] = src[(k0 + 1) * DD + n];
        v[2] = src[(k0 + 8) * DD + n];
        v[3] = src[(k0 + 9) * DD + n];
        __half h[4], l[4];
#pragma unroll
        for (int i = 0; i < 4; ++i) {
            h[i] = __float2half_rn(v[i]);
            l[i] = __float2half_rn(v[i] - __half2float(h[i]));
        }
        unsigned* o = g_Bpack + m * 16384 + s * 4;
        o[0] = packh2(h[0], h[1]);
        o[1] = packh2(h[2], h[3]);
        o[2] = packh2(l[0], l[1]);
        o[3] = packh2(l[2], l[3]);
    }
}

// ---- packed fp32x2 helpers (aggregate phase, B300 FFMA2) ----
__device__ __forceinline__ void fma2(ull& acc, ull a, ull w) {
    asm("fma.rn.f32x2 %0, %1, %2, %0;" : "+l"(acc) : "l"(a), "l"(w));
}
__device__ __forceinline__ ull dup2(float v) {
    ull r;
    asm("mov.b64 %0, {%1, %1};" : "=l"(r) : "r"(__float_as_uint(v)));
    return r;
}

// ---- cp.async helpers ----
__device__ __forceinline__ void cp_async16(unsigned int s, const void* g) {
    asm volatile("cp.async.ca.shared.global [%0], [%1], 16;" :: "r"(s), "l"(g));
}
#define CP_COMMIT() asm volatile("cp.async.commit_group;")
#define CP_WAIT1()  asm volatile("cp.async.wait_group 1;")
#define CP_WAIT0()  asm volatile("cp.async.wait_group 0;")

__device__ __forceinline__ void mma_f16(float c[4], const unsigned a[4],
                                        unsigned b0, unsigned b1) {
    asm("mma.sync.aligned.m16n8k16.row.col.f32.f16.f16.f32 "
        "{%0,%1,%2,%3},{%4,%5,%6,%7},{%8,%9},{%0,%1,%2,%3};"
        : "+f"(c[0]), "+f"(c[1]), "+f"(c[2]), "+f"(c[3])
        : "r"(a[0]), "r"(a[1]), "r"(a[2]), "r"(a[3]), "r"(b0), "r"(b1));
}

// Convert fp32 A (64x128 row-major, smem) into fragment-ordered fp16 hi/lo:
// dst[s] hi, dst[4096+s] lo; s = ((rt*8+ks)*32+lane)*4 + j
__device__ __forceinline__ void convert_A(const float* __restrict__ A,
                                          unsigned* __restrict__ dst, int tid) {
    for (int s = tid; s < 4096; s += 256) {
        const int j = s & 3, lane = (s >> 2) & 31, ks = (s >> 7) & 7, rt = s >> 10;
        const int row = rt * 16 + (lane >> 2) + ((j & 1) << 3);
        const int col = ks * 16 + (lane & 3) * 2 + ((j & 2) << 2);
        const float v0 = A[row * DD + col], v1 = A[row * DD + col + 1];
        const __half h0 = __float2half_rn(v0), h1 = __float2half_rn(v1);
        const __half l0 = __float2half_rn(v0 - __half2float(h0));
        const __half l1 = __float2half_rn(v1 - __half2float(h1));
        dst[s]        = packh2(h0, h1);
        dst[4096 + s] = packh2(l0, l1);
    }
}

// Same, but A = T0 computed on the fly from global inputs.
__device__ __forceinline__ void convert_T0(const int* __restrict__ x,
                                           const float* __restrict__ attr_emb,
                                           const float* __restrict__ opt_emb,
                                           const float* __restrict__ prior,
                                           int b, unsigned* __restrict__ dst, int tid) {
    for (int s = tid; s < 4096; s += 256) {
        const int j = s & 3, lane = (s >> 2) & 31, ks = (s >> 7) & 7, rt = s >> 10;
        const int row = rt * 16 + (lane >> 2) + ((j & 1) << 3);
        const int col = ks * 16 + (lane & 3) * 2 + ((j & 2) << 2);
        const int xv = x[b * NN + row];
        const float pr = prior[row];
        const float v0 = (attr_emb[row * DD + col] + opt_emb[(row * KK + xv) * DD + col]) * pr;
        const float v1 = (attr_emb[row * DD + col + 1] + opt_emb[(row * KK + xv) * DD + col + 1]) * pr;
        const __half h0 = __float2half_rn(v0), h1 = __float2half_rn(v1);
        const __half l0 = __float2half_rn(v0 - __half2float(h0));
        const __half l1 = __float2half_rn(v1 - __half2float(h1));
        dst[s]        = packh2(h0, h1);
        dst[4096 + s] = packh2(l0, l1);
    }
}

// 64x128 @ 128x128 accumulate via m16n8k16 fp16 hi/lo (3-term split).
// Warp tile: rows rt*16..+16, cols cg*64..+64 (8 n8 coltiles). B streamed via
// double-buffered 2x8KB panel (1 kstep per chunk) from fragment-packed global.
__device__ __forceinline__ void gemm_mma(float c[8][4], const unsigned* __restrict__ Af,
                                         const unsigned* __restrict__ Bp,
                                         unsigned* __restrict__ panel,
                                         int tid, int lane, int rt, int cg) {
    const unsigned p0 = (unsigned)__cvta_generic_to_shared(panel);
    cp_async16(p0 + tid * 32,      Bp + tid * 8);
    cp_async16(p0 + tid * 32 + 16, Bp + tid * 8 + 4);
    CP_COMMIT();
#pragma unroll 1
    for (int ks = 0; ks < 8; ++ks) {
        if (ks < 7) {
            const unsigned pb = p0 + ((ks + 1) & 1) * 8192 + tid * 32;
            const unsigned* g = Bp + (ks + 1) * 2048 + tid * 8;
            cp_async16(pb, g);
            cp_async16(pb + 16, g + 4);
            CP_COMMIT();
            CP_WAIT1();
        } else {
            CP_WAIT0();
        }
        __syncthreads();
        const unsigned* P = panel + (ks & 1) * 2048;
        unsigned ah[4], al[4];
        *(uint4*)ah = *(const uint4*)&Af[((rt * 8 + ks) * 32 + lane) * 4];
        *(uint4*)al = *(const uint4*)&Af[4096 + ((rt * 8 + ks) * 32 + lane) * 4];
#pragma unroll
        for (int i = 0; i < 8; ++i) {
            const uint4 B = *(const uint4*)&P[((cg * 8 + i) * 32 + lane) * 4];
            mma_f16(c[i], ah, B.x, B.y);   // hi*hi
            mma_f16(c[i], ah, B.z, B.w);   // hi*lo
            mma_f16(c[i], al, B.x, B.y);   // lo*hi
        }
        __syncthreads();
    }
}

__device__ __forceinline__ void cinit(float c[8][4], const float* __restrict__ bias,
                                      int cg, int lane) {
#pragma unroll
    for (int i = 0; i < 8; ++i) {
        const int col = (cg * 8 + i) * 8 + (lane & 3) * 2;
        c[i][0] = bias[col];
        c[i][1] = bias[col + 1];
        c[i][2] = c[i][0];
        c[i][3] = c[i][1];
    }
}

__device__ __forceinline__ void cstore(const float c[8][4], float* __restrict__ dst,
                                       int rt, int cg, int lane) {
    const int row = rt * 16 + (lane >> 2);
#pragma unroll
    for (int i = 0; i < 8; ++i) {
        const int col = (cg * 8 + i) * 8 + (lane & 3) * 2;
        *(float2*)(dst + row * DD + col)       = make_float2(c[i][0], c[i][1]);
        *(float2*)(dst + (row + 8) * DD + col) = make_float2(c[i][2], c[i][3]);
    }
}

__device__ __forceinline__ void cstore_relu(const float c[8][4], float* __restrict__ dst,
                                            int rt, int cg, int lane) {
    const int row = rt * 16 + (lane >> 2);
#pragma unroll
    for (int i = 0; i < 8; ++i) {
        const int col = (cg * 8 + i) * 8 + (lane & 3) * 2;
        *(float2*)(dst + row * DD + col) =
            make_float2(fmaxf(c[i][0], 0.f), fmaxf(c[i][1], 0.f));
        *(float2*)(dst + (row + 8) * DD + col) =
            make_float2(fmaxf(c[i][2], 0.f), fmaxf(c[i][3], 0.f));
    }
}

__global__ __launch_bounds__(256, 2) void gat_kernel(
    const int* __restrict__ x,
    const float* __restrict__ attr_emb, const float* __restrict__ opt_emb,
    const float* __restrict__ prior,
    const float* __restrict__ bl, const float* __restrict__ br,
    const float* __restrict__ We, const float* __restrict__ att,
    const float* __restrict__ conv_bias, const float* __restrict__ ln_g,
    const float* __restrict__ ln_b,
    const float* __restrict__ b1,
    const float* __restrict__ W2, const float* __restrict__ b2,
    float* __restrict__ out) {
    extern __shared__ float sm[];
    float* h_s   = sm;                     // 8192 floats (h; starts as T0)
    float* xl_s  = h_s + NN * DD;          // 8192
    float* xr_s  = xl_s + NN * DD;         // 8192 (A-fp16 frags / xr / aggregate out)
    float* un_s  = xr_s + NN * DD;         // 4096: union{ B panel | alpha[H][EE] | epilogue }
    unsigned char* esrc_s = (unsigned char*)(un_s + HH * EE);  // 1024 B

    const int b = blockIdx.x;
    const int tid = threadIdx.x;
    const int lane = tid & 31;
    const int w = tid >> 5;                // 0..7
    const int g_rt = w & 3;                // GEMM rowtile
    const int g_cg = w >> 2;               // GEMM colgroup

    unsigned* af_s = (unsigned*)xr_s;      // A-fragment buffer (hi 16KB + lo 16KB)
    unsigned* pan_s = (unsigned*)un_s;     // B panel (2 x 8KB)

    // ---- load packed src indices ----
    for (int e = tid; e < EE; e += 256) esrc_s[e] = (unsigned char)g_srcp[e];

    // ---- h = T0 = (attr_emb + opt_emb[n, x]) * prior ----
    for (int idx = tid; idx < NN * DD; idx += 256) {
        const int n = idx >> 7, d = idx & 127;
        const int xv = x[b * NN + n];
        h_s[idx] = (attr_emb[idx] + opt_emb[(n * KK + xv) * DD + d]) * prior[n];
    }
    __syncthreads();

    for (int l = 0; l < LL; ++l) {
        // ---- convert h to fp16 hi/lo fragments (into xr_s) ----
        convert_A(h_s, af_s, tid);
        __syncthreads();

        // ---- xl = h@Wl + bl ; xr = h@Wr + br  (tensor core, fp16 3-term) ----
        {
            float c[8][4];
            cinit(c, bl + l * DD, g_cg, lane);
            gemm_mma(c, af_s, g_Bpack + (2 * l) * 16384, pan_s, tid, lane, g_rt, g_cg);
            cstore(c, xl_s, g_rt, g_cg, lane);

            cinit(c, br + l * DD, g_cg, lane);
            gemm_mma(c, af_s, g_Bpack + (2 * l + 1) * 16384, pan_s, tid, lane, g_rt, g_cg);
            cstore(c, xr_s, g_rt, g_cg, lane);   // overwrites A-frags (all reads done)
        }
        __syncthreads();

        float* alpha_s = un_s;             // [H][EE]

        // ---- alpha: warp per destination node ----
        {
            const int head = lane >> 3;
            const float4 We4  = *(const float4*)(We  + l * DD + lane * 4);
            const float4 att4 = *(const float4*)(att + l * DD + lane * 4);
            for (int n = w; n < NN; n += 8) {
                const float4 xr4 = *(const float4*)(xr_s + n * DD + lane * 4);
                const int e0 = g_off[n], e1 = g_off[n + 1];
#pragma unroll 2
                for (int i = e0; i < e1; ++i) {
                    const int s = esrc_s[i];
                    const float eav = g_eap[i];
                    const float4 xl4 = *(const float4*)(xl_s + s * DD + lane * 4);
                    float z0 = xl4.x + xr4.x + eav * We4.x;
                    float z1 = xl4.y + xr4.y + eav * We4.y;
                    float z2 = xl4.z + xr4.z + eav * We4.z;
                    float z3 = xl4.w + xr4.w + eav * We4.w;
                    z0 = z0 > 0.f ? z0 : 0.2f * z0;
                    z1 = z1 > 0.f ? z1 : 0.2f * z1;
                    z2 = z2 > 0.f ? z2 : 0.2f * z2;
                    z3 = z3 > 0.f ? z3 : 0.2f * z3;
                    float p = z0 * att4.x + z1 * att4.y + z2 * att4.z + z3 * att4.w;
                    p += __shfl_xor_sync(0xffffffffu, p, 1);
                    p += __shfl_xor_sync(0xffffffffu, p, 2);
                    p += __shfl_xor_sync(0xffffffffu, p, 4);
                    if ((lane & 7) == 0) alpha_s[head * EE + i] = p;
                }
            }
        }
        __syncthreads();

        // ---- softmax per node: warp-parallel, lanes = (8 edges) x (4 heads) ----
        {
            const int head = lane >> 3;
            const int el   = lane & 7;
            float* a = alpha_s + head * EE;
            for (int n = w; n < NN; n += 8) {
                const int e0 = g_off[n], e1 = g_off[n + 1];
                float m = -INFINITY;
                for (int i = e0 + el; i < e1; i += 8) m = fmaxf(m, a[i]);
                m = fmaxf(m, __shfl_xor_sync(0xffffffffu, m, 1));
                m = fmaxf(m, __shfl_xor_sync(0xffffffffu, m, 2));
                m = fmaxf(m, __shfl_xor_sync(0xffffffffu, m, 4));
                float s = 0.f;
                for (int i = e0 + el; i < e1; i += 8) {
                    const float ex = __expf(a[i] - m);
                    a[i] = ex;
                    s += ex;
                }
                s += __shfl_xor_sync(0xffffffffu, s, 1);
                s += __shfl_xor_sync(0xffffffffu, s, 2);
                s += __shfl_xor_sync(0xffffffffu, s, 4);
                const float inv = 1.f / s;
                for (int i = e0 + el; i < e1; i += 8) a[i] *= inv;
            }
        }
        __syncthreads();

        // ---- aggregate (f32x2): out[n,d] = sum_in xl[src,d]*a  (into xr_s) ----
        {
            const int dp = tid & 63;       // d-pair -> d = dp*2
            const int q = tid >> 6;        // 0..3
            const float* a = alpha_s + (dp >> 4) * EE;
            for (int n = q; n < NN; n += 4) {
                ull acc = 0ull;
                const int e0 = g_off[n], e1 = g_off[n + 1];
#pragma unroll 4
                for (int i = e0; i < e1; ++i) {
                    const ull xv = *(const ull*)(xl_s + (int)esrc_s[i] * DD + dp * 2);
                    fma2(acc, xv, dup2(a[i]));
                }
                *(ull*)(xr_s + n * DD + dp * 2) = acc;
            }
        }
        __syncthreads();

        // ---- g = LN(out + conv_bias); h += elu(g)   (warp per node) ----
        for (int n = w; n < NN; n += 8) {
            const float4 gv = *(const float4*)(xr_s + n * DD + lane * 4);
            float v[4];
            v[0] = gv.x + conv_bias[l * DD + lane * 4 + 0];
            v[1] = gv.y + conv_bias[l * DD + lane * 4 + 1];
            v[2] = gv.z + conv_bias[l * DD + lane * 4 + 2];
            v[3] = gv.w + conv_bias[l * DD + lane * 4 + 3];
            float sum = v[0] + v[1] + v[2] + v[3];
            float sq  = v[0]*v[0] + v[1]*v[1] + v[2]*v[2] + v[3]*v[3];
#pragma unroll
            for (int o = 16; o; o >>= 1) {
                sum += __shfl_xor_sync(0xffffffffu, sum, o);
                sq  += __shfl_xor_sync(0xffffffffu, sq, o);
            }
            const float mu = sum * (1.f / DD);
            const float var = sq * (1.f / DD) - mu * mu;
            const float rstd = rsqrtf(var + 1e-5f);
#pragma unroll
            for (int i = 0; i < 4; ++i) {
                const int d = lane * 4 + i;
                float t = (v[i] - mu) * rstd * ln_g[l * DD + d] + ln_b[l * DD + d];
                t = t > 0.f ? t : expm1f(t);
                h_s[n * DD + d] += t;
            }
        }
        __syncthreads();
    }

    // ---- MLP: q = relu([T0, h] @ W1 + b1) -> xl_s  (two K=128 MMA passes) ----
    {
        float c[8][4];
        cinit(c, b1, g_cg, lane);
        convert_T0(x, attr_emb, opt_emb, prior, b, af_s, tid);
        __syncthreads();
        gemm_mma(c, af_s, g_Bpack + 4 * 16384, pan_s, tid, lane, g_rt, g_cg);
        convert_A(h_s, af_s, tid);     // gemm's final sync guards the overwrite
        __syncthreads();
        gemm_mma(c, af_s, g_Bpack + 5 * 16384, pan_s, tid, lane, g_rt, g_cg);
        cstore_relu(c, xl_s, g_rt, g_cg, lane);
    }
    __syncthreads();

    float* rel_s = un_s;          // [0..63], relsum at [64], partials at [128..384)

    // ---- rel[n] = sigmoid(q[n].W2 + b2)   (warp per node) ----
    {
        const long long OR = (long long)NB * DD;
        const float4 w24 = *(const float4*)(W2 + lane * 4);
        for (int n = w; n < NN; n += 8) {
            const float4 qv = *(const float4*)(xl_s + n * DD + lane * 4);
            float p = qv.x * w24.x + qv.y * w24.y + qv.z * w24.z + qv.w * w24.w;
#pragma unroll
            for (int o = 16; o; o >>= 1) p += __shfl_xor_sync(0xffffffffu, p, o);
            if (lane == 0) {
                const float r = 1.f / (1.f + expf(-(p + b2[0])));
                rel_s[n] = r;
                out[OR + (long long)b * NN + n] = r;
            }
        }
    }
    __syncthreads();

    // ---- rel sum (warp 0) ----
    if (w == 0) {
        float v = rel_s[lane] + rel_s[lane + 32];
#pragma unroll
        for (int o = 16; o; o >>= 1) v += __shfl_xor_sync(0xffffffffu, v, o);
        if (lane == 0) rel_s[64] = v;
    }

    // ---- f_scale partials ----
    {
        const int d = tid & 127;
        const int q = tid >> 7;            // 0..1
        float acc = 0.f;
        for (int n = q; n < NN; n += 2)
            acc = fmaf(h_s[n * DD + d], rel_s[n], acc);
        un_s[128 + q * DD + d] = acc;
    }

    // ---- hat_T output: [T0 (recomputed), h] ----
    {
        const long long OH = (long long)NB * DD + (long long)NB * NN;
        for (int idx = tid; idx < NN * DD; idx += 256) {
            const int n = idx >> 7, d = idx & 127;
            const int xv = x[b * NN + n];
            const float t0 = (attr_emb[idx] + opt_emb[(n * KK + xv) * DD + d]) * prior[n];
            const long long base = OH + ((long long)b * NN + n) * (2 * DD);
            out[base + d] = t0;
            out[base + DD + d] = h_s[idx];
        }
    }
    __syncthreads();

    if (tid < DD) {
        const float num = un_s[128 + tid] + un_s[256 + tid];
        out[(long long)b * DD + tid] = num / (rel_s[64] + 1e-8f);
    }
}

extern "C" void kernel_launch(void* const* d_in, const int* in_sizes, int n_in,
                              void* d_out, int out_size) {
    const int*   x         = (const int*)d_in[0];
    const int*   ei        = (const int*)d_in[1];
    const float* ea        = (const float*)d_in[2];
    const float* attr_emb  = (const float*)d_in[3];
    const float* opt_emb   = (const float*)d_in[4];
    const float* prior     = (const float*)d_in[5];
    const float* Wl        = (const float*)d_in[6];
    const float* bl        = (const float*)d_in[7];
    const float* Wr        = (const float*)d_in[8];
    const float* br        = (const float*)d_in[9];
    const float* We        = (const float*)d_in[10];
    const float* att       = (const float*)d_in[11];
    const float* conv_bias = (const float*)d_in[12];
    const float* ln_g      = (const float*)d_in[13];
    const float* ln_b      = (const float*)d_in[14];
    const float* W1        = (const float*)d_in[15];
    const float* b1        = (const float*)d_in[16];
    const float* W2        = (const float*)d_in[17];
    const float* b2        = (const float*)d_in[18];
    float* out = (float*)d_out;

    const size_t smem = 3 * NN * DD * sizeof(float) + HH * EE * sizeof(float) + EE;
    cudaFuncSetAttribute(gat_kernel, cudaFuncAttributeMaxDynamicSharedMemorySize, (int)smem);

    build_csr_fast<<<1, EE>>>(ei, ea);
    pack_w_kernel<<<6, 256>>>(Wl, Wr, W1);
    gat_kernel<<<NB, 256, smem>>>(x, attr_emb, opt_emb, prior,
                                  bl, br, We, att, conv_bias,
                                  ln_g, ln_b, b1, W2, b2, out);
}

// round 11
// speedup vs baseline: 1.9757x; 1.0337x over previous
#include <cuda_runtime.h>
#include <cuda_bf16.h>
#include <cuda_fp16.h>
#include <math.h>

#define NB 1024   // batches
#define NN 64     // nodes
#define DD 128    // feature dim
#define EE 1024   // edges
#define HH 4      // heads
#define KK 5
#define LL 2

// Edge data sorted by dst (CSR order), built once per launch
__device__ int   g_off[NN + 1];
__device__ int   g_srcp[EE];
__device__ float g_eap[EE];

// W matrices as fp16 hi/lo packed in m16n8k16 B-fragment order (see pack_w_kernel).
// mats: 0=Wl0 1=Wr0 2=Wl1 3=Wr1 4=W1[0:128] 5=W1[128:256]
__device__ unsigned g_Bpack[6 * 16384];

__global__ __launch_bounds__(EE) void build_csr_fast(const int* __restrict__ ei,
                                                     const float* __restrict__ ea) {
    __shared__ int dstS[EE];
    __shared__ int degS[NN];
    __shared__ int offS[NN + 1];
    const int e = threadIdx.x;
    if (e < NN) degS[e] = 0;
    __syncthreads();
    const int d = ei[EE + e];
    dstS[e] = d;
    atomicAdd(&degS[d], 1);
    __syncthreads();
    if (e == 0) {
        int s = 0;
        for (int i = 0; i < NN; ++i) { offS[i] = s; s += degS[i]; }
        offS[NN] = s;
    }
    __syncthreads();
    int rank = 0;
    for (int j = 0; j < e; ++j) rank += (dstS[j] == d);
    const int p = offS[d] + rank;
    g_srcp[p] = ei[e];
    g_eap[p]  = ea[e];
    if (e <= NN) g_off[e] = offS[e];
}

__device__ __forceinline__ unsigned packh2(__half a, __half b) {
    __half2 h; h.x = a; h.y = b;
    return *(const unsigned*)&h;
}

__global__ void pack_w_kernel(const float* __restrict__ Wl, const float* __restrict__ Wr,
                              const float* __restrict__ W1) {
    const int m = blockIdx.x;            // 0..5
    const float* src = (m == 0) ? Wl : (m == 1) ? Wr : (m == 2) ? Wl + 16384
                     : (m == 3) ? Wr + 16384 : (m == 4) ? W1 : W1 + 16384;
    for (int s = threadIdx.x; s < 4096; s += blockDim.x) {
        const int lane = s & 31, ct = (s >> 5) & 15, ks = s >> 9;
        const int n  = ct * 8 + (lane >> 2);
        const int k0 = ks * 16 + (lane & 3) * 2;
        float v[4];
        v[0] = src[(k0)     * DD + n];
        v[1] = src[(k0 + 1) * DD + n];
        v[2] = src[(k0 + 8) * DD + n];
        v[3] = src[(k0 + 9) * DD + n];
        __half h[4], l[4];
#pragma unroll
        for (int i = 0; i < 4; ++i) {
            h[i] = __float2half_rn(v[i]);
            l[i] = __float2half_rn(v[i] - __half2float(h[i]));
        }
        unsigned* o = g_Bpack + m * 16384 + s * 4;
        o[0] = packh2(h[0], h[1]);
        o[1] = packh2(h[2], h[3]);
        o[2] = packh2(l[0], l[1]);
        o[3] = packh2(l[2], l[3]);
    }
}

// ---- cp.async helpers ----
__device__ __forceinline__ void cp_async16(unsigned int s, const void* g) {
    asm volatile("cp.async.ca.shared.global [%0], [%1], 16;" :: "r"(s), "l"(g));
}
#define CP_COMMIT() asm volatile("cp.async.commit_group;")
#define CP_WAIT0()  asm volatile("cp.async.wait_group 0;")

__device__ __forceinline__ void mma_f16(float c[4], const unsigned a[4],
                                        unsigned b0, unsigned b1) {
    asm("mma.sync.aligned.m16n8k16.row.col.f32.f16.f16.f32 "
        "{%0,%1,%2,%3},{%4,%5,%6,%7},{%8,%9},{%0,%1,%2,%3};"
        : "+f"(c[0]), "+f"(c[1]), "+f"(c[2]), "+f"(c[3])
        : "r"(a[0]), "r"(a[1]), "r"(a[2]), "r"(a[3]), "r"(b0), "r"(b1));
}

// Convert fp32 A (64x128 row-major, smem) into fragment-ordered fp16 hi/lo.
__device__ __forceinline__ void convert_A(const float* __restrict__ A,
                                          unsigned* __restrict__ dst, int tid) {
    for (int s = tid; s < 4096; s += 256) {
        const int j = s & 3, lane = (s >> 2) & 31, ks = (s >> 7) & 7, rt = s >> 10;
        const int row = rt * 16 + (lane >> 2) + ((j & 1) << 3);
        const int col = ks * 16 + (lane & 3) * 2 + ((j & 2) << 2);
        const float v0 = A[row * DD + col], v1 = A[row * DD + col + 1];
        const __half h0 = __float2half_rn(v0), h1 = __float2half_rn(v1);
        const __half l0 = __float2half_rn(v0 - __half2float(h0));
        const __half l1 = __float2half_rn(v1 - __half2float(h1));
        dst[s]        = packh2(h0, h1);
        dst[4096 + s] = packh2(l0, l1);
    }
}

__device__ __forceinline__ void convert_T0(const int* __restrict__ x,
                                           const float* __restrict__ attr_emb,
                                           const float* __restrict__ opt_emb,
                                           const float* __restrict__ prior,
                                           int b, unsigned* __restrict__ dst, int tid) {
    for (int s = tid; s < 4096; s += 256) {
        const int j = s & 3, lane = (s >> 2) & 31, ks = (s >> 7) & 7, rt = s >> 10;
        const int row = rt * 16 + (lane >> 2) + ((j & 1) << 3);
        const int col = ks * 16 + (lane & 3) * 2 + ((j & 2) << 2);
        const int xv = x[b * NN + row];
        const float pr = prior[row];
        const float v0 = (attr_emb[row * DD + col] + opt_emb[(row * KK + xv) * DD + col]) * pr;
        const float v1 = (attr_emb[row * DD + col + 1] + opt_emb[(row * KK + xv) * DD + col + 1]) * pr;
        const __half h0 = __float2half_rn(v0), h1 = __float2half_rn(v1);
        const __half l0 = __float2half_rn(v0 - __half2float(h0));
        const __half l1 = __float2half_rn(v1 - __half2float(h1));
        dst[s]        = packh2(h0, h1);
        dst[4096 + s] = packh2(l0, l1);
    }
}

// common MMA kstep body
__device__ __forceinline__ void mma_kstep(float c[8][4], const unsigned* __restrict__ Af,
                                          const unsigned* __restrict__ P,
                                          int ks, int lane, int rt, int cg) {
    unsigned ah[4], al[4];
    *(uint4*)ah = *(const uint4*)&Af[((rt * 8 + ks) * 32 + lane) * 4];
    *(uint4*)al = *(const uint4*)&Af[4096 + ((rt * 8 + ks) * 32 + lane) * 4];
#pragma unroll
    for (int i = 0; i < 8; ++i) {
        const uint4 B = *(const uint4*)&P[((cg * 8 + i) * 32 + lane) * 4];
        mma_f16(c[i], ah, B.x, B.y);   // hi*hi
        mma_f16(c[i], ah, B.z, B.w);   // hi*lo
        mma_f16(c[i], al, B.x, B.y);   // lo*hi
    }
}

// GEMM with 2-kstep chunks, panel = 2 x 16KB (in xl_s). 1 sync per chunk + trailing.
__device__ __forceinline__ void gemm_mma2(float c[8][4], const unsigned* __restrict__ Af,
                                          const unsigned* __restrict__ Bp,
                                          unsigned* __restrict__ panel,
                                          int tid, int lane, int rt, int cg) {
    const unsigned p0 = (unsigned)__cvta_generic_to_shared(panel);
#pragma unroll
    for (int j = 0; j < 4; ++j)
        cp_async16(p0 + tid * 64 + j * 16, Bp + tid * 16 + j * 4);
    CP_COMMIT();
#pragma unroll 1
    for (int ch = 0; ch < 4; ++ch) {
        CP_WAIT0();
        __syncthreads();
        if (ch < 3) {
            const unsigned pb = p0 + ((ch + 1) & 1) * 16384 + tid * 64;
            const unsigned* g = Bp + (ch + 1) * 4096 + tid * 16;
#pragma unroll
            for (int j = 0; j < 4; ++j) cp_async16(pb + j * 16, g + j * 4);
            CP_COMMIT();
        }
        const unsigned* P = panel + (ch & 1) * 4096;
        mma_kstep(c, Af, P,        ch * 2,     lane, rt, cg);
        mma_kstep(c, Af, P + 2048, ch * 2 + 1, lane, rt, cg);
    }
    __syncthreads();
}

// GEMM with 1-kstep chunks, panel = 2 x 8KB (in un_s). 1 sync per chunk + trailing.
__device__ __forceinline__ void gemm_mma1(float c[8][4], const unsigned* __restrict__ Af,
                                          const unsigned* __restrict__ Bp,
                                          unsigned* __restrict__ panel,
                                          int tid, int lane, int rt, int cg) {
    const unsigned p0 = (unsigned)__cvta_generic_to_shared(panel);
    cp_async16(p0 + tid * 32,      Bp + tid * 8);
    cp_async16(p0 + tid * 32 + 16, Bp + tid * 8 + 4);
    CP_COMMIT();
#pragma unroll 1
    for (int ch = 0; ch < 8; ++ch) {
        CP_WAIT0();
        __syncthreads();
        if (ch < 7) {
            const unsigned pb = p0 + ((ch + 1) & 1) * 8192 + tid * 32;
            const unsigned* g = Bp + (ch + 1) * 2048 + tid * 8;
            cp_async16(pb, g);
            cp_async16(pb + 16, g + 4);
            CP_COMMIT();
        }
        mma_kstep(c, Af, panel + (ch & 1) * 2048, ch, lane, rt, cg);
    }
    __syncthreads();
}

__device__ __forceinline__ void cinit(float c[8][4], const float* __restrict__ bias,
                                      int cg, int lane) {
#pragma unroll
    for (int i = 0; i < 8; ++i) {
        const int col = (cg * 8 + i) * 8 + (lane & 3) * 2;
        c[i][0] = bias[col];
        c[i][1] = bias[col + 1];
        c[i][2] = c[i][0];
        c[i][3] = c[i][1];
    }
}

__device__ __forceinline__ void cstore(const float c[8][4], float* __restrict__ dst,
                                       int rt, int cg, int lane) {
    const int row = rt * 16 + (lane >> 2);
#pragma unroll
    for (int i = 0; i < 8; ++i) {
        const int col = (cg * 8 + i) * 8 + (lane & 3) * 2;
        *(float2*)(dst + row * DD + col)       = make_float2(c[i][0], c[i][1]);
        *(float2*)(dst + (row + 8) * DD + col) = make_float2(c[i][2], c[i][3]);
    }
}

__device__ __forceinline__ void cstore_relu(const float c[8][4], float* __restrict__ dst,
                                            int rt, int cg, int lane) {
    const int row = rt * 16 + (lane >> 2);
#pragma unroll
    for (int i = 0; i < 8; ++i) {
        const int col = (cg * 8 + i) * 8 + (lane & 3) * 2;
        *(float2*)(dst + row * DD + col) =
            make_float2(fmaxf(c[i][0], 0.f), fmaxf(c[i][1], 0.f));
        *(float2*)(dst + (row + 8) * DD + col) =
            make_float2(fmaxf(c[i][2], 0.f), fmaxf(c[i][3], 0.f));
    }
}

__global__ __launch_bounds__(256, 2) void gat_kernel(
    const int* __restrict__ x,
    const float* __restrict__ attr_emb, const float* __restrict__ opt_emb,
    const float* __restrict__ prior,
    const float* __restrict__ bl, const float* __restrict__ br,
    const float* __restrict__ We, const float* __restrict__ att,
    const float* __restrict__ conv_bias, const float* __restrict__ ln_g,
    const float* __restrict__ ln_b,
    const float* __restrict__ b1,
    const float* __restrict__ W2, const float* __restrict__ b2,
    float* __restrict__ out) {
    extern __shared__ float sm[];
    float* h_s   = sm;                     // 8192 floats (h; starts as T0)
    float* xl_s  = h_s + NN * DD;          // 8192 (also 32KB GEMM panel when dead)
    float* xr_s  = xl_s + NN * DD;         // 8192 (A-fp16 frags / xr)
    float* un_s  = xr_s + NN * DD;         // 4096: union{ small panel | alpha[H][EE] | epilogue }
    unsigned char* esrc_s = (unsigned char*)(un_s + HH * EE);  // 1024 B

    const int b = blockIdx.x;
    const int tid = threadIdx.x;
    const int lane = tid & 31;
    const int w = tid >> 5;                // 0..7
    const int g_rt = w & 3;                // GEMM rowtile
    const int g_cg = w >> 2;               // GEMM colgroup

    unsigned* af_s   = (unsigned*)xr_s;    // A-fragment buffer (hi 16KB + lo 16KB)
    unsigned* panB_s = (unsigned*)xl_s;    // big panel (2 x 16KB)
    unsigned* panS_s = (unsigned*)un_s;    // small panel (2 x 8KB)

    // ---- load packed src indices ----
    for (int e = tid; e < EE; e += 256) esrc_s[e] = (unsigned char)g_srcp[e];

    // ---- h = T0 = (attr_emb + opt_emb[n, x]) * prior ----
    for (int idx = tid; idx < NN * DD; idx += 256) {
        const int n = idx >> 7, d = idx & 127;
        const int xv = x[b * NN + n];
        h_s[idx] = (attr_emb[idx] + opt_emb[(n * KK + xv) * DD + d]) * prior[n];
    }
    __syncthreads();

    for (int l = 0; l < LL; ++l) {
        // ---- convert h to fp16 hi/lo fragments (into xr_s) ----
        convert_A(h_s, af_s, tid);
        __syncthreads();

        // ---- xl = h@Wl + bl (big panel in xl_s) ; xr = h@Wr + br (small panel) ----
        {
            float c[8][4];
            cinit(c, bl + l * DD, g_cg, lane);
            gemm_mma2(c, af_s, g_Bpack + (2 * l) * 16384, panB_s, tid, lane, g_rt, g_cg);
            cstore(c, xl_s, g_rt, g_cg, lane);   // panel dead after trailing sync

            cinit(c, br + l * DD, g_cg, lane);
            gemm_mma1(c, af_s, g_Bpack + (2 * l + 1) * 16384, panS_s, tid, lane, g_rt, g_cg);
            cstore(c, xr_s, g_rt, g_cg, lane);   // overwrites A-frags (reads done)
        }
        __syncthreads();                         // publish xl, xr to all warps

        // ======== fused edge phase: alpha -> softmax -> aggregate+LN ========
        // warp w owns nodes {w, w+8, ...}; all cross-lane data stays in-warp.
        float* alpha_s = un_s;                   // [H][EE]
        const int head = lane >> 3;
        const int el   = lane & 7;

        // ---- alpha ----
        {
            const float4 We4  = *(const float4*)(We  + l * DD + lane * 4);
            const float4 att4 = *(const float4*)(att + l * DD + lane * 4);
            for (int n = w; n < NN; n += 8) {
                const float4 xr4 = *(const float4*)(xr_s + n * DD + lane * 4);
                const int e0 = g_off[n], e1 = g_off[n + 1];
#pragma unroll 2
                for (int i = e0; i < e1; ++i) {
                    const int s = esrc_s[i];
                    const float eav = g_eap[i];
                    const float4 xl4 = *(const float4*)(xl_s + s * DD + lane * 4);
                    float z0 = xl4.x + xr4.x + eav * We4.x;
                    float z1 = xl4.y + xr4.y + eav * We4.y;
                    float z2 = xl4.z + xr4.z + eav * We4.z;
                    float z3 = xl4.w + xr4.w + eav * We4.w;
                    z0 = z0 > 0.f ? z0 : 0.2f * z0;
                    z1 = z1 > 0.f ? z1 : 0.2f * z1;
                    z2 = z2 > 0.f ? z2 : 0.2f * z2;
                    z3 = z3 > 0.f ? z3 : 0.2f * z3;
                    float p = z0 * att4.x + z1 * att4.y + z2 * att4.z + z3 * att4.w;
                    p += __shfl_xor_sync(0xffffffffu, p, 1);
                    p += __shfl_xor_sync(0xffffffffu, p, 2);
                    p += __shfl_xor_sync(0xffffffffu, p, 4);
                    if (el == 0) alpha_s[head * EE + i] = p;
                }
            }
        }
        __syncwarp();

        // ---- softmax per node (own nodes only) ----
        {
            float* a = alpha_s + head * EE;
            for (int n = w; n < NN; n += 8) {
                const int e0 = g_off[n], e1 = g_off[n + 1];
                float m = -INFINITY;
                for (int i = e0 + el; i < e1; i += 8) m = fmaxf(m, a[i]);
                m = fmaxf(m, __shfl_xor_sync(0xffffffffu, m, 1));
                m = fmaxf(m, __shfl_xor_sync(0xffffffffu, m, 2));
                m = fmaxf(m, __shfl_xor_sync(0xffffffffu, m, 4));
                float s = 0.f;
                for (int i = e0 + el; i < e1; i += 8) {
                    const float ex = __expf(a[i] - m);
                    a[i] = ex;
                    s += ex;
                }
                s += __shfl_xor_sync(0xffffffffu, s, 1);
                s += __shfl_xor_sync(0xffffffffu, s, 2);
                s += __shfl_xor_sync(0xffffffffu, s, 4);
                const float inv = 1.f / s;
                for (int i = e0 + el; i < e1; i += 8) a[i] *= inv;
            }
        }
        __syncwarp();

        // ---- aggregate (row in regs) + LN + h update ----
        {
            const float4 cb4 = *(const float4*)(conv_bias + l * DD + lane * 4);
            const float4 lg4 = *(const float4*)(ln_g + l * DD + lane * 4);
            const float4 lb4 = *(const float4*)(ln_b + l * DD + lane * 4);
            const float* a = alpha_s + head * EE;
            for (int n = w; n < NN; n += 8) {
                const int e0 = g_off[n], e1 = g_off[n + 1];
                float v0 = 0.f, v1 = 0.f, v2 = 0.f, v3 = 0.f;
#pragma unroll 2
                for (int i = e0; i < e1; ++i) {
                    const float av = a[i];
                    const float4 xl4 = *(const float4*)(xl_s + (int)esrc_s[i] * DD + lane * 4);
                    v0 = fmaf(xl4.x, av, v0);
                    v1 = fmaf(xl4.y, av, v1);
                    v2 = fmaf(xl4.z, av, v2);
                    v3 = fmaf(xl4.w, av, v3);
                }
                v0 += cb4.x; v1 += cb4.y; v2 += cb4.z; v3 += cb4.w;
                float sum = v0 + v1 + v2 + v3;
                float sq  = v0*v0 + v1*v1 + v2*v2 + v3*v3;
#pragma unroll
                for (int o = 16; o; o >>= 1) {
                    sum += __shfl_xor_sync(0xffffffffu, sum, o);
                    sq  += __shfl_xor_sync(0xffffffffu, sq, o);
                }
                const float mu = sum * (1.f / DD);
                const float var = sq * (1.f / DD) - mu * mu;
                const float rstd = rsqrtf(var + 1e-5f);
                float t0v = (v0 - mu) * rstd * lg4.x + lb4.x;
                float t1v = (v1 - mu) * rstd * lg4.y + lb4.y;
                float t2v = (v2 - mu) * rstd * lg4.z + lb4.z;
                float t3v = (v3 - mu) * rstd * lg4.w + lb4.w;
                t0v = t0v > 0.f ? t0v : expm1f(t0v);
                t1v = t1v > 0.f ? t1v : expm1f(t1v);
                t2v = t2v > 0.f ? t2v : expm1f(t2v);
                t3v = t3v > 0.f ? t3v : expm1f(t3v);
                float4 hv = *(const float4*)(h_s + n * DD + lane * 4);
                hv.x += t0v; hv.y += t1v; hv.z += t2v; hv.w += t3v;
                *(float4*)(h_s + n * DD + lane * 4) = hv;
            }
        }
        __syncthreads();                   // publish h before next convert
    }

    // ---- MLP: q = relu([T0, h] @ W1 + b1) -> xl_s  (two K=128 MMA passes) ----
    {
        float c[8][4];
        cinit(c, b1, g_cg, lane);
        convert_T0(x, attr_emb, opt_emb, prior, b, af_s, tid);
        __syncthreads();
        gemm_mma2(c, af_s, g_Bpack + 4 * 16384, panB_s, tid, lane, g_rt, g_cg);
        convert_A(h_s, af_s, tid);         // trailing sync of gemm guards overwrite
        __syncthreads();
        gemm_mma2(c, af_s, g_Bpack + 5 * 16384, panB_s, tid, lane, g_rt, g_cg);
        cstore_relu(c, xl_s, g_rt, g_cg, lane);
    }
    __syncthreads();

    float* rel_s = un_s;          // [0..63], relsum at [64], partials at [128..384)

    // ---- rel[n] = sigmoid(q[n].W2 + b2)   (warp per node) ----
    {
        const long long OR = (long long)NB * DD;
        const float4 w24 = *(const float4*)(W2 + lane * 4);
        for (int n = w; n < NN; n += 8) {
            const float4 qv = *(const float4*)(xl_s + n * DD + lane * 4);
            float p = qv.x * w24.x + qv.y * w24.y + qv.z * w24.z + qv.w * w24.w;
#pragma unroll
            for (int o = 16; o; o >>= 1) p += __shfl_xor_sync(0xffffffffu, p, o);
            if (lane == 0) {
                const float r = 1.f / (1.f + expf(-(p + b2[0])));
                rel_s[n] = r;
                out[OR + (long long)b * NN + n] = r;
            }
        }
    }
    __syncthreads();

    // ---- rel sum (warp 0) ----
    if (w == 0) {
        float v = rel_s[lane] + rel_s[lane + 32];
#pragma unroll
        for (int o = 16; o; o >>= 1) v += __shfl_xor_sync(0xffffffffu, v, o);
        if (lane == 0) rel_s[64] = v;
    }

    // ---- f_scale partials ----
    {
        const int d = tid & 127;
        const int q = tid >> 7;            // 0..1
        float acc = 0.f;
        for (int n = q; n < NN; n += 2)
            acc = fmaf(h_s[n * DD + d], rel_s[n], acc);
        un_s[128 + q * DD + d] = acc;
    }

    // ---- hat_T output: [T0 (recomputed), h] ----
    {
        const long long OH = (long long)NB * DD + (long long)NB * NN;
        for (int idx = tid; idx < NN * DD; idx += 256) {
            const int n = idx >> 7, d = idx & 127;
            const int xv = x[b * NN + n];
            const float t0 = (attr_emb[idx] + opt_emb[(n * KK + xv) * DD + d]) * prior[n];
            const long long base = OH + ((long long)b * NN + n) * (2 * DD);
            out[base + d] = t0;
            out[base + DD + d] = h_s[idx];
        }
    }
    __syncthreads();

    if (tid < DD) {
        const float num = un_s[128 + tid] + un_s[256 + tid];
        out[(long long)b * DD + tid] = num / (rel_s[64] + 1e-8f);
    }
}

extern "C" void kernel_launch(void* const* d_in, const int* in_sizes, int n_in,
                              void* d_out, int out_size) {
    const int*   x         = (const int*)d_in[0];
    const int*   ei        = (const int*)d_in[1];
    const float* ea        = (const float*)d_in[2];
    const float* attr_emb  = (const float*)d_in[3];
    const float* opt_emb   = (const float*)d_in[4];
    const float* prior     = (const float*)d_in[5];
    const float* Wl        = (const float*)d_in[6];
    const float* bl        = (const float*)d_in[7];
    const float* Wr        = (const float*)d_in[8];
    const float* br        = (const float*)d_in[9];
    const float* We        = (const float*)d_in[10];
    const float* att       = (const float*)d_in[11];
    const float* conv_bias = (const float*)d_in[12];
    const float* ln_g      = (const float*)d_in[13];
    const float* ln_b      = (const float*)d_in[14];
    const float* W1        = (const float*)d_in[15];
    const float* b1        = (const float*)d_in[16];
    const float* W2        = (const float*)d_in[17];
    const float* b2        = (const float*)d_in[18];
    float* out = (float*)d_out;

    const size_t smem = 3 * NN * DD * sizeof(float) + HH * EE * sizeof(float) + EE;
    cudaFuncSetAttribute(gat_kernel, cudaFuncAttributeMaxDynamicSharedMemorySize, (int)smem);

    build_csr_fast<<<1, EE>>>(ei, ea);
    pack_w_kernel<<<6, 256>>>(Wl, Wr, W1);
    gat_kernel<<<NB, 256, smem>>>(x, attr_emb, opt_emb, prior,
                                  bl, br, We, att, conv_bias,
                                  ln_g, ln_b, b1, W2, b2, out);
}

// round 12
// speedup vs baseline: 2.1788x; 1.1028x over previous
#include <cuda_runtime.h>
#include <cuda_bf16.h>
#include <cuda_fp16.h>
#include <math.h>

#define NB 1024   // batches
#define NN 64     // nodes
#define DD 128    // feature dim
#define EE 1024   // edges
#define HH 4      // heads
#define KK 5
#define LL 2

// Edge data sorted by dst (CSR order), built once per launch
__device__ int   g_off[NN + 1];
__device__ int   g_srcp[EE];
__device__ float g_eap[EE];

// W matrices as fp16 hi/lo packed in m16n8k16 B-fragment order:
// mat m: slot s = (ks*16 + ct)*32 + lane; u32[4] = {bhi0, bhi1, blo0, blo1}
// mats: 0=Wl0 1=Wr0 2=Wl1 3=Wr1 4=W1[0:128] 5=W1[128:256]
__device__ unsigned g_Bpack[6 * 16384];

__device__ __forceinline__ unsigned packh2(__half a, __half b) {
    __half2 h; h.x = a; h.y = b;
    return *(const unsigned*)&h;
}

// Merged setup: block 0 = CSR build (1024 threads), blocks 1..6 = W packing.
__global__ __launch_bounds__(EE) void setup_kernel(const int* __restrict__ ei,
                                                   const float* __restrict__ ea,
                                                   const float* __restrict__ Wl,
                                                   const float* __restrict__ Wr,
                                                   const float* __restrict__ W1) {
    if (blockIdx.x == 0) {
        __shared__ int dstS[EE];
        __shared__ int degS[NN];
        __shared__ int offS[NN + 1];
        const int e = threadIdx.x;
        if (e < NN) degS[e] = 0;
        __syncthreads();
        const int d = ei[EE + e];
        dstS[e] = d;
        atomicAdd(&degS[d], 1);
        __syncthreads();
        if (e == 0) {
            int s = 0;
            for (int i = 0; i < NN; ++i) { offS[i] = s; s += degS[i]; }
            offS[NN] = s;
        }
        __syncthreads();
        int rank = 0;
        for (int j = 0; j < e; ++j) rank += (dstS[j] == d);
        const int p = offS[d] + rank;
        g_srcp[p] = ei[e];
        g_eap[p]  = ea[e];
        if (e <= NN) g_off[e] = offS[e];
    } else {
        const int m = blockIdx.x - 1;    // 0..5
        const float* src = (m == 0) ? Wl : (m == 1) ? Wr : (m == 2) ? Wl + 16384
                         : (m == 3) ? Wr + 16384 : (m == 4) ? W1 : W1 + 16384;
        for (int s = threadIdx.x; s < 4096; s += blockDim.x) {
            const int lane = s & 31, ct = (s >> 5) & 15, ks = s >> 9;
            const int n  = ct * 8 + (lane >> 2);
            const int k0 = ks * 16 + (lane & 3) * 2;
            float v[4];
            v[0] = src[(k0)     * DD + n];
            v[1] = src[(k0 + 1) * DD + n];
            v[2] = src[(k0 + 8) * DD + n];
            v[3] = src[(k0 + 9) * DD + n];
            __half h[4], l[4];
#pragma unroll
            for (int i = 0; i < 4; ++i) {
                h[i] = __float2half_rn(v[i]);
                l[i] = __float2half_rn(v[i] - __half2float(h[i]));
            }
            unsigned* o = g_Bpack + m * 16384 + s * 4;
            o[0] = packh2(h[0], h[1]);
            o[1] = packh2(h[2], h[3]);
            o[2] = packh2(l[0], l[1]);
            o[3] = packh2(l[2], l[3]);
        }
    }
}

__device__ __forceinline__ void mma_f16(float c[4], const unsigned a[4],
                                        unsigned b0, unsigned b1) {
    asm("mma.sync.aligned.m16n8k16.row.col.f32.f16.f16.f32 "
        "{%0,%1,%2,%3},{%4,%5,%6,%7},{%8,%9},{%0,%1,%2,%3};"
        : "+f"(c[0]), "+f"(c[1]), "+f"(c[2]), "+f"(c[3])
        : "r"(a[0]), "r"(a[1]), "r"(a[2]), "r"(a[3]), "r"(b0), "r"(b1));
}

// Convert fp32 A (64x128 row-major, smem) into fragment-ordered fp16 hi/lo.
__device__ __forceinline__ void convert_A(const float* __restrict__ A,
                                          unsigned* __restrict__ dst, int tid) {
    for (int s = tid; s < 4096; s += 256) {
        const int j = s & 3, lane = (s >> 2) & 31, ks = (s >> 7) & 7, rt = s >> 10;
        const int row = rt * 16 + (lane >> 2) + ((j & 1) << 3);
        const int col = ks * 16 + (lane & 3) * 2 + ((j & 2) << 2);
        const float v0 = A[row * DD + col], v1 = A[row * DD + col + 1];
        const __half h0 = __float2half_rn(v0), h1 = __float2half_rn(v1);
        const __half l0 = __float2half_rn(v0 - __half2float(h0));
        const __half l1 = __float2half_rn(v1 - __half2float(h1));
        dst[s]        = packh2(h0, h1);
        dst[4096 + s] = packh2(l0, l1);
    }
}

__device__ __forceinline__ void convert_T0(const int* __restrict__ x,
                                           const float* __restrict__ attr_emb,
                                           const float* __restrict__ opt_emb,
                                           const float* __restrict__ prior,
                                           int b, unsigned* __restrict__ dst, int tid) {
    for (int s = tid; s < 4096; s += 256) {
        const int j = s & 3, lane = (s >> 2) & 31, ks = (s >> 7) & 7, rt = s >> 10;
        const int row = rt * 16 + (lane >> 2) + ((j & 1) << 3);
        const int col = ks * 16 + (lane & 3) * 2 + ((j & 2) << 2);
        const int xv = x[b * NN + row];
        const float pr = prior[row];
        const float v0 = (attr_emb[row * DD + col] + opt_emb[(row * KK + xv) * DD + col]) * pr;
        const float v1 = (attr_emb[row * DD + col + 1] + opt_emb[(row * KK + xv) * DD + col + 1]) * pr;
        const __half h0 = __float2half_rn(v0), h1 = __float2half_rn(v1);
        const __half l0 = __float2half_rn(v0 - __half2float(h0));
        const __half l1 = __float2half_rn(v1 - __half2float(h1));
        dst[s]        = packh2(h0, h1);
        dst[4096 + s] = packh2(l0, l1);
    }
}

// 64x128 @ 128x128 accumulate, B read DIRECTLY from global (L1-resident,
// fragment-ordered) — no smem staging, no cp.async, no __syncthreads.
// Warp tile: rows rt*16..+16, cols cg*64..+64.
__device__ __forceinline__ void gemm_ld(float c[8][4], const unsigned* __restrict__ Af,
                                        const unsigned* __restrict__ Bp,
                                        int lane, int rt, int cg) {
#pragma unroll 2
    for (int ks = 0; ks < 8; ++ks) {
        unsigned ah[4], al[4];
        *(uint4*)ah = *(const uint4*)&Af[((rt * 8 + ks) * 32 + lane) * 4];
        *(uint4*)al = *(const uint4*)&Af[4096 + ((rt * 8 + ks) * 32 + lane) * 4];
#pragma unroll
        for (int g = 0; g < 2; ++g) {
            uint4 B[4];
#pragma unroll
            for (int j = 0; j < 4; ++j)
                B[j] = *(const uint4*)&Bp[((ks * 16 + cg * 8 + g * 4 + j) * 32 + lane) * 4];
#pragma unroll
            for (int j = 0; j < 4; ++j) mma_f16(c[g * 4 + j], ah, B[j].x, B[j].y);
#pragma unroll
            for (int j = 0; j < 4; ++j) mma_f16(c[g * 4 + j], ah, B[j].z, B[j].w);
#pragma unroll
            for (int j = 0; j < 4; ++j) mma_f16(c[g * 4 + j], al, B[j].x, B[j].y);
        }
    }
}

__device__ __forceinline__ void cinit(float c[8][4], const float* __restrict__ bias,
                                      int cg, int lane) {
#pragma unroll
    for (int i = 0; i < 8; ++i) {
        const int col = (cg * 8 + i) * 8 + (lane & 3) * 2;
        c[i][0] = bias[col];
        c[i][1] = bias[col + 1];
        c[i][2] = c[i][0];
        c[i][3] = c[i][1];
    }
}

__device__ __forceinline__ void cstore(const float c[8][4], float* __restrict__ dst,
                                       int rt, int cg, int lane) {
    const int row = rt * 16 + (lane >> 2);
#pragma unroll
    for (int i = 0; i < 8; ++i) {
        const int col = (cg * 8 + i) * 8 + (lane & 3) * 2;
        *(float2*)(dst + row * DD + col)       = make_float2(c[i][0], c[i][1]);
        *(float2*)(dst + (row + 8) * DD + col) = make_float2(c[i][2], c[i][3]);
    }
}

__device__ __forceinline__ void cstore_relu(const float c[8][4], float* __restrict__ dst,
                                            int rt, int cg, int lane) {
    const int row = rt * 16 + (lane >> 2);
#pragma unroll
    for (int i = 0; i < 8; ++i) {
        const int col = (cg * 8 + i) * 8 + (lane & 3) * 2;
        *(float2*)(dst + row * DD + col) =
            make_float2(fmaxf(c[i][0], 0.f), fmaxf(c[i][1], 0.f));
        *(float2*)(dst + (row + 8) * DD + col) =
            make_float2(fmaxf(c[i][2], 0.f), fmaxf(c[i][3], 0.f));
    }
}

__global__ __launch_bounds__(256, 2) void gat_kernel(
    const int* __restrict__ x,
    const float* __restrict__ attr_emb, const float* __restrict__ opt_emb,
    const float* __restrict__ prior,
    const float* __restrict__ bl, const float* __restrict__ br,
    const float* __restrict__ We, const float* __restrict__ att,
    const float* __restrict__ conv_bias, const float* __restrict__ ln_g,
    const float* __restrict__ ln_b,
    const float* __restrict__ b1,
    const float* __restrict__ W2, const float* __restrict__ b2,
    float* __restrict__ out) {
    extern __shared__ float sm[];
    float* h_s   = sm;                     // 8192 floats (h; starts as T0)
    float* xl_s  = h_s + NN * DD;          // 8192
    float* xr_s  = xl_s + NN * DD;         // 8192 (A-fp16 frags / xr)
    float* un_s  = xr_s + NN * DD;         // 4096: union{ alpha[H][EE] | epilogue }
    unsigned char* esrc_s = (unsigned char*)(un_s + HH * EE);  // 1024 B

    const int b = blockIdx.x;
    const int tid = threadIdx.x;
    const int lane = tid & 31;
    const int w = tid >> 5;                // 0..7
    const int g_rt = w & 3;                // GEMM rowtile
    const int g_cg = w >> 2;               // GEMM colgroup

    unsigned* af_s = (unsigned*)xr_s;      // A-fragment buffer (hi 16KB + lo 16KB)

    // ---- load packed src indices ----
    for (int e = tid; e < EE; e += 256) esrc_s[e] = (unsigned char)g_srcp[e];

    // ---- h = T0 = (attr_emb + opt_emb[n, x]) * prior ----
    for (int idx = tid; idx < NN * DD; idx += 256) {
        const int n = idx >> 7, d = idx & 127;
        const int xv = x[b * NN + n];
        h_s[idx] = (attr_emb[idx] + opt_emb[(n * KK + xv) * DD + d]) * prior[n];
    }
    __syncthreads();

    for (int l = 0; l < LL; ++l) {
        // ---- convert h to fp16 hi/lo fragments (into xr_s) ----
        convert_A(h_s, af_s, tid);
        __syncthreads();

        // ---- xl = h@Wl + bl ; xr = h@Wr + br  (direct-LDG B, no staging) ----
        {
            float c[8][4];
            cinit(c, bl + l * DD, g_cg, lane);
            gemm_ld(c, af_s, g_Bpack + (2 * l) * 16384, lane, g_rt, g_cg);
            cstore(c, xl_s, g_rt, g_cg, lane);

            cinit(c, br + l * DD, g_cg, lane);
            gemm_ld(c, af_s, g_Bpack + (2 * l + 1) * 16384, lane, g_rt, g_cg);
            __syncthreads();                     // all warps done reading A-frags
            cstore(c, xr_s, g_rt, g_cg, lane);   // safe: overwrites af region
        }
        __syncthreads();                         // publish xl, xr

        // ======== fused edge phase: alpha -> softmax -> aggregate+LN ========
        float* alpha_s = un_s;                   // [H][EE]
        const int head = lane >> 3;
        const int el   = lane & 7;

        // ---- alpha ----
        {
            const float4 We4  = *(const float4*)(We  + l * DD + lane * 4);
            const float4 att4 = *(const float4*)(att + l * DD + lane * 4);
            for (int n = w; n < NN; n += 8) {
                const float4 xr4 = *(const float4*)(xr_s + n * DD + lane * 4);
                const int e0 = g_off[n], e1 = g_off[n + 1];
#pragma unroll 2
                for (int i = e0; i < e1; ++i) {
                    const int s = esrc_s[i];
                    const float eav = g_eap[i];
                    const float4 xl4 = *(const float4*)(xl_s + s * DD + lane * 4);
                    float z0 = xl4.x + xr4.x + eav * We4.x;
                    float z1 = xl4.y + xr4.y + eav * We4.y;
                    float z2 = xl4.z + xr4.z + eav * We4.z;
                    float z3 = xl4.w + xr4.w + eav * We4.w;
                    z0 = z0 > 0.f ? z0 : 0.2f * z0;
                    z1 = z1 > 0.f ? z1 : 0.2f * z1;
                    z2 = z2 > 0.f ? z2 : 0.2f * z2;
                    z3 = z3 > 0.f ? z3 : 0.2f * z3;
                    float p = z0 * att4.x + z1 * att4.y + z2 * att4.z + z3 * att4.w;
                    p += __shfl_xor_sync(0xffffffffu, p, 1);
                    p += __shfl_xor_sync(0xffffffffu, p, 2);
                    p += __shfl_xor_sync(0xffffffffu, p, 4);
                    if (el == 0) alpha_s[head * EE + i] = p;
                }
            }
        }
        __syncwarp();

        // ---- softmax per node (own nodes only) ----
        {
            float* a = alpha_s + head * EE;
            for (int n = w; n < NN; n += 8) {
                const int e0 = g_off[n], e1 = g_off[n + 1];
                float m = -INFINITY;
                for (int i = e0 + el; i < e1; i += 8) m = fmaxf(m, a[i]);
                m = fmaxf(m, __shfl_xor_sync(0xffffffffu, m, 1));
                m = fmaxf(m, __shfl_xor_sync(0xffffffffu, m, 2));
                m = fmaxf(m, __shfl_xor_sync(0xffffffffu, m, 4));
                float s = 0.f;
                for (int i = e0 + el; i < e1; i += 8) {
                    const float ex = __expf(a[i] - m);
                    a[i] = ex;
                    s += ex;
                }
                s += __shfl_xor_sync(0xffffffffu, s, 1);
                s += __shfl_xor_sync(0xffffffffu, s, 2);
                s += __shfl_xor_sync(0xffffffffu, s, 4);
                const float inv = 1.f / s;
                for (int i = e0 + el; i < e1; i += 8) a[i] *= inv;
            }
        }
        __syncwarp();

        // ---- aggregate (row in regs) + LN + h update ----
        {
            const float4 cb4 = *(const float4*)(conv_bias + l * DD + lane * 4);
            const float4 lg4 = *(const float4*)(ln_g + l * DD + lane * 4);
            const float4 lb4 = *(const float4*)(ln_b + l * DD + lane * 4);
            const float* a = alpha_s + head * EE;
            for (int n = w; n < NN; n += 8) {
                const int e0 = g_off[n], e1 = g_off[n + 1];
                float v0 = 0.f, v1 = 0.f, v2 = 0.f, v3 = 0.f;
#pragma unroll 2
                for (int i = e0; i < e1; ++i) {
                    const float av = a[i];
                    const float4 xl4 = *(const float4*)(xl_s + (int)esrc_s[i] * DD + lane * 4);
                    v0 = fmaf(xl4.x, av, v0);
                    v1 = fmaf(xl4.y, av, v1);
                    v2 = fmaf(xl4.z, av, v2);
                    v3 = fmaf(xl4.w, av, v3);
                }
                v0 += cb4.x; v1 += cb4.y; v2 += cb4.z; v3 += cb4.w;
                float sum = v0 + v1 + v2 + v3;
                float sq  = v0*v0 + v1*v1 + v2*v2 + v3*v3;
#pragma unroll
                for (int o = 16; o; o >>= 1) {
                    sum += __shfl_xor_sync(0xffffffffu, sum, o);
                    sq  += __shfl_xor_sync(0xffffffffu, sq, o);
                }
                const float mu = sum * (1.f / DD);
                const float var = sq * (1.f / DD) - mu * mu;
                const float rstd = rsqrtf(var + 1e-5f);
                float t0v = (v0 - mu) * rstd * lg4.x + lb4.x;
                float t1v = (v1 - mu) * rstd * lg4.y + lb4.y;
                float t2v = (v2 - mu) * rstd * lg4.z + lb4.z;
                float t3v = (v3 - mu) * rstd * lg4.w + lb4.w;
                t0v = t0v > 0.f ? t0v : expm1f(t0v);
                t1v = t1v > 0.f ? t1v : expm1f(t1v);
                t2v = t2v > 0.f ? t2v : expm1f(t2v);
                t3v = t3v > 0.f ? t3v : expm1f(t3v);
                float4 hv = *(const float4*)(h_s + n * DD + lane * 4);
                hv.x += t0v; hv.y += t1v; hv.z += t2v; hv.w += t3v;
                *(float4*)(h_s + n * DD + lane * 4) = hv;
            }
        }
        __syncthreads();                   // publish h before next convert
    }

    // ---- MLP: q = relu([T0, h] @ W1 + b1) -> xl_s  (two K=128 passes) ----
    {
        float c[8][4];
        cinit(c, b1, g_cg, lane);
        convert_T0(x, attr_emb, opt_emb, prior, b, af_s, tid);
        __syncthreads();
        gemm_ld(c, af_s, g_Bpack + 4 * 16384, lane, g_rt, g_cg);
        __syncthreads();                   // all warps done with T0 frags
        convert_A(h_s, af_s, tid);
        __syncthreads();
        gemm_ld(c, af_s, g_Bpack + 5 * 16384, lane, g_rt, g_cg);
        cstore_relu(c, xl_s, g_rt, g_cg, lane);
    }
    __syncthreads();

    float* rel_s = un_s;          // [0..63], relsum at [64], partials at [128..384)

    // ---- rel[n] = sigmoid(q[n].W2 + b2)   (warp per node) ----
    {
        const long long OR = (long long)NB * DD;
        const float4 w24 = *(const float4*)(W2 + lane * 4);
        for (int n = w; n < NN; n += 8) {
            const float4 qv = *(const float4*)(xl_s + n * DD + lane * 4);
            float p = qv.x * w24.x + qv.y * w24.y + qv.z * w24.z + qv.w * w24.w;
#pragma unroll
            for (int o = 16; o; o >>= 1) p += __shfl_xor_sync(0xffffffffu, p, o);
            if (lane == 0) {
                const float r = 1.f / (1.f + expf(-(p + b2[0])));
                rel_s[n] = r;
                out[OR + (long long)b * NN + n] = r;
            }
        }
    }
    __syncthreads();

    // ---- rel sum (warp 0) ----
    if (w == 0) {
        float v = rel_s[lane] + rel_s[lane + 32];
#pragma unroll
        for (int o = 16; o; o >>= 1) v += __shfl_xor_sync(0xffffffffu, v, o);
        if (lane == 0) rel_s[64] = v;
    }

    // ---- f_scale partials ----
    {
        const int d = tid & 127;
        const int q = tid >> 7;            // 0..1
        float acc = 0.f;
        for (int n = q; n < NN; n += 2)
            acc = fmaf(h_s[n * DD + d], rel_s[n], acc);
        un_s[128 + q * DD + d] = acc;
    }

    // ---- hat_T output: [T0 (recomputed), h] ----
    {
        const long long OH = (long long)NB * DD + (long long)NB * NN;
        for (int idx = tid; idx < NN * DD; idx += 256) {
            const int n = idx >> 7, d = idx & 127;
            const int xv = x[b * NN + n];
            const float t0 = (attr_emb[idx] + opt_emb[(n * KK + xv) * DD + d]) * prior[n];
            const long long base = OH + ((long long)b * NN + n) * (2 * DD);
            out[base + d] = t0;
            out[base + DD + d] = h_s[idx];
        }
    }
    __syncthreads();

    if (tid < DD) {
        const float num = un_s[128 + tid] + un_s[256 + tid];
        out[(long long)b * DD + tid] = num / (rel_s[64] + 1e-8f);
    }
}

extern "C" void kernel_launch(void* const* d_in, const int* in_sizes, int n_in,
                              void* d_out, int out_size) {
    const int*   x         = (const int*)d_in[0];
    const int*   ei        = (const int*)d_in[1];
    const float* ea        = (const float*)d_in[2];
    const float* attr_emb  = (const float*)d_in[3];
    const float* opt_emb   = (const float*)d_in[4];
    const float* prior     = (const float*)d_in[5];
    const float* Wl        = (const float*)d_in[6];
    const float* bl        = (const float*)d_in[7];
    const float* Wr        = (const float*)d_in[8];
    const float* br        = (const float*)d_in[9];
    const float* We        = (const float*)d_in[10];
    const float* att       = (const float*)d_in[11];
    const float* conv_bias = (const float*)d_in[12];
    const float* ln_g      = (const float*)d_in[13];
    const float* ln_b      = (const float*)d_in[14];
    const float* W1        = (const float*)d_in[15];
    const float* b1        = (const float*)d_in[16];
    const float* W2        = (const float*)d_in[17];
    const float* b2        = (const float*)d_in[18];
    float* out = (float*)d_out;

    const size_t smem = 3 * NN * DD * sizeof(float) + HH * EE * sizeof(float) + EE;
    cudaFuncSetAttribute(gat_kernel, cudaFuncAttributeMaxDynamicSharedMemorySize, (int)smem);

    setup_kernel<<<7, EE>>>(ei, ea, Wl, Wr, W1);
    gat_kernel<<<NB, 256, smem>>>(x, attr_emb, opt_emb, prior,
                                  bl, br, We, att, conv_bias,
                                  ln_g, ln_b, b1, W2, b2, out);
}

// round 13
// speedup vs baseline: 2.4835x; 1.1398x over previous
#include <cuda_runtime.h>
#include <cuda_bf16.h>
#include <cuda_fp16.h>
#include <math.h>

#define NB 1024   // batches
#define NN 64     // nodes
#define DD 128    // feature dim
#define EE 1024   // edges
#define HH 4      // heads
#define KK 5
#define LL 2
#define NT 384    // threads per CTA
#define NW 12     // warps per CTA

// Edge data sorted by dst (CSR order), built once per launch
__device__ int   g_off[NN + 1];
__device__ int   g_srcp[EE];
__device__ float g_eap[EE];

// W matrices as fp16 hi/lo packed in m16n8k16 B-fragment order:
// mat m: slot s = (ks*16 + ct)*32 + lane; u32[4] = {bhi0, bhi1, blo0, blo1}
// mats: 0=Wl0 1=Wr0 2=Wl1 3=Wr1 4=W1[0:128] 5=W1[128:256]
__device__ unsigned g_Bpack[6 * 16384];

__device__ __forceinline__ unsigned packh2(__half a, __half b) {
    __half2 h; h.x = a; h.y = b;
    return *(const unsigned*)&h;
}

// Merged setup: block 0 = CSR build (1024 threads), blocks 1..6 = W packing.
__global__ __launch_bounds__(EE) void setup_kernel(const int* __restrict__ ei,
                                                   const float* __restrict__ ea,
                                                   const float* __restrict__ Wl,
                                                   const float* __restrict__ Wr,
                                                   const float* __restrict__ W1) {
    if (blockIdx.x == 0) {
        __shared__ int dstS[EE];
        __shared__ int degS[NN];
        __shared__ int offS[NN + 1];
        const int e = threadIdx.x;
        if (e < NN) degS[e] = 0;
        __syncthreads();
        const int d = ei[EE + e];
        dstS[e] = d;
        atomicAdd(&degS[d], 1);
        __syncthreads();
        if (e == 0) {
            int s = 0;
            for (int i = 0; i < NN; ++i) { offS[i] = s; s += degS[i]; }
            offS[NN] = s;
        }
        __syncthreads();
        int rank = 0;
        for (int j = 0; j < e; ++j) rank += (dstS[j] == d);
        const int p = offS[d] + rank;
        g_srcp[p] = ei[e];
        g_eap[p]  = ea[e];
        if (e <= NN) g_off[e] = offS[e];
    } else {
        const int m = blockIdx.x - 1;    // 0..5
        const float* src = (m == 0) ? Wl : (m == 1) ? Wr : (m == 2) ? Wl + 16384
                         : (m == 3) ? Wr + 16384 : (m == 4) ? W1 : W1 + 16384;
        for (int s = threadIdx.x; s < 4096; s += blockDim.x) {
            const int lane = s & 31, ct = (s >> 5) & 15, ks = s >> 9;
            const int n  = ct * 8 + (lane >> 2);
            const int k0 = ks * 16 + (lane & 3) * 2;
            float v[4];
            v[0] = src[(k0)     * DD + n];
            v[1] = src[(k0 + 1) * DD + n];
            v[2] = src[(k0 + 8) * DD + n];
            v[3] = src[(k0 + 9) * DD + n];
            __half h[4], l[4];
#pragma unroll
            for (int i = 0; i < 4; ++i) {
                h[i] = __float2half_rn(v[i]);
                l[i] = __float2half_rn(v[i] - __half2float(h[i]));
            }
            unsigned* o = g_Bpack + m * 16384 + s * 4;
            o[0] = packh2(h[0], h[1]);
            o[1] = packh2(h[2], h[3]);
            o[2] = packh2(l[0], l[1]);
            o[3] = packh2(l[2], l[3]);
        }
    }
}

__device__ __forceinline__ void mma_f16(float c[4], const unsigned a[4],
                                        unsigned b0, unsigned b1) {
    asm("mma.sync.aligned.m16n8k16.row.col.f32.f16.f16.f32 "
        "{%0,%1,%2,%3},{%4,%5,%6,%7},{%8,%9},{%0,%1,%2,%3};"
        : "+f"(c[0]), "+f"(c[1]), "+f"(c[2]), "+f"(c[3])
        : "r"(a[0]), "r"(a[1]), "r"(a[2]), "r"(a[3]), "r"(b0), "r"(b1));
}

// Convert fp32 A (64x128 row-major, smem) into fragment-ordered fp16 hi/lo.
__device__ __forceinline__ void convert_A(const float* __restrict__ A,
                                          unsigned* __restrict__ dst, int tid) {
    for (int s = tid; s < 4096; s += NT) {
        const int j = s & 3, lane = (s >> 2) & 31, ks = (s >> 7) & 7, rt = s >> 10;
        const int row = rt * 16 + (lane >> 2) + ((j & 1) << 3);
        const int col = ks * 16 + (lane & 3) * 2 + ((j & 2) << 2);
        const float v0 = A[row * DD + col], v1 = A[row * DD + col + 1];
        const __half h0 = __float2half_rn(v0), h1 = __float2half_rn(v1);
        const __half l0 = __float2half_rn(v0 - __half2float(h0));
        const __half l1 = __float2half_rn(v1 - __half2float(h1));
        dst[s]        = packh2(h0, h1);
        dst[4096 + s] = packh2(l0, l1);
    }
}

__device__ __forceinline__ void convert_T0(const int* __restrict__ x,
                                           const float* __restrict__ attr_emb,
                                           const float* __restrict__ opt_emb,
                                           const float* __restrict__ prior,
                                           int b, unsigned* __restrict__ dst, int tid) {
    for (int s = tid; s < 4096; s += NT) {
        const int j = s & 3, lane = (s >> 2) & 31, ks = (s >> 7) & 7, rt = s >> 10;
        const int row = rt * 16 + (lane >> 2) + ((j & 1) << 3);
        const int col = ks * 16 + (lane & 3) * 2 + ((j & 2) << 2);
        const int xv = x[b * NN + row];
        const float pr = prior[row];
        const float v0 = (attr_emb[row * DD + col] + opt_emb[(row * KK + xv) * DD + col]) * pr;
        const float v1 = (attr_emb[row * DD + col + 1] + opt_emb[(row * KK + xv) * DD + col + 1]) * pr;
        const __half h0 = __float2half_rn(v0), h1 = __float2half_rn(v1);
        const __half l0 = __float2half_rn(v0 - __half2float(h0));
        const __half l1 = __float2half_rn(v1 - __half2float(h1));
        dst[s]        = packh2(h0, h1);
        dst[4096 + s] = packh2(l0, l1);
    }
}

// 64x128 @ 128x128 accumulate, B read DIRECTLY from global (L1-resident).
// Warp (rt, grp): rows rt*16..+16, coltiles ct = grp + 3*j (j < nt; nt=6 if grp==0 else 5).
__device__ __forceinline__ void gemm_ld(float c[6][4], const unsigned* __restrict__ Af,
                                        const unsigned* __restrict__ Bp,
                                        int lane, int rt, int grp, int nt) {
#pragma unroll 2
    for (int ks = 0; ks < 8; ++ks) {
        unsigned ah[4], al[4];
        *(uint4*)ah = *(const uint4*)&Af[((rt * 8 + ks) * 32 + lane) * 4];
        *(uint4*)al = *(const uint4*)&Af[4096 + ((rt * 8 + ks) * 32 + lane) * 4];
        uint4 B[6];
#pragma unroll
        for (int j = 0; j < 6; ++j)
            if (j < nt)
                B[j] = *(const uint4*)&Bp[((ks * 16 + grp + 3 * j) * 32 + lane) * 4];
#pragma unroll
        for (int j = 0; j < 6; ++j) if (j < nt) mma_f16(c[j], ah, B[j].x, B[j].y);
#pragma unroll
        for (int j = 0; j < 6; ++j) if (j < nt) mma_f16(c[j], ah, B[j].z, B[j].w);
#pragma unroll
        for (int j = 0; j < 6; ++j) if (j < nt) mma_f16(c[j], al, B[j].x, B[j].y);
    }
}

__device__ __forceinline__ void cinit(float c[6][4], const float* __restrict__ bias,
                                      int grp, int lane, int nt) {
#pragma unroll
    for (int j = 0; j < 6; ++j) {
        if (j < nt) {
            const int col = (grp + 3 * j) * 8 + (lane & 3) * 2;
            c[j][0] = bias[col];
            c[j][1] = bias[col + 1];
            c[j][2] = c[j][0];
            c[j][3] = c[j][1];
        }
    }
}

__device__ __forceinline__ void cstore(const float c[6][4], float* __restrict__ dst,
                                       int rt, int grp, int lane, int nt) {
    const int row = rt * 16 + (lane >> 2);
#pragma unroll
    for (int j = 0; j < 6; ++j) {
        if (j < nt) {
            const int col = (grp + 3 * j) * 8 + (lane & 3) * 2;
            *(float2*)(dst + row * DD + col)       = make_float2(c[j][0], c[j][1]);
            *(float2*)(dst + (row + 8) * DD + col) = make_float2(c[j][2], c[j][3]);
        }
    }
}

__device__ __forceinline__ void cstore_relu(const float c[6][4], float* __restrict__ dst,
                                            int rt, int grp, int lane, int nt) {
    const int row = rt * 16 + (lane >> 2);
#pragma unroll
    for (int j = 0; j < 6; ++j) {
        if (j < nt) {
            const int col = (grp + 3 * j) * 8 + (lane & 3) * 2;
            *(float2*)(dst + row * DD + col) =
                make_float2(fmaxf(c[j][0], 0.f), fmaxf(c[j][1], 0.f));
            *(float2*)(dst + (row + 8) * DD + col) =
                make_float2(fmaxf(c[j][2], 0.f), fmaxf(c[j][3], 0.f));
        }
    }
}

__global__ __launch_bounds__(NT, 2) void gat_kernel(
    const int* __restrict__ x,
    const float* __restrict__ attr_emb, const float* __restrict__ opt_emb,
    const float* __restrict__ prior,
    const float* __restrict__ bl, const float* __restrict__ br,
    const float* __restrict__ We, const float* __restrict__ att,
    const float* __restrict__ conv_bias, const float* __restrict__ ln_g,
    const float* __restrict__ ln_b,
    const float* __restrict__ b1,
    const float* __restrict__ W2, const float* __restrict__ b2,
    float* __restrict__ out) {
    extern __shared__ float sm[];
    float* h_s   = sm;                     // 8192 floats (h; starts as T0)
    float* xl_s  = h_s + NN * DD;          // 8192
    float* xr_s  = xl_s + NN * DD;         // 8192 (A-fp16 frags / xr)
    float* un_s  = xr_s + NN * DD;         // 4096: union{ alpha[H][EE] | epilogue }
    unsigned char* esrc_s = (unsigned char*)(un_s + HH * EE);  // 1024 B

    const int b = blockIdx.x;
    const int tid = threadIdx.x;
    const int lane = tid & 31;
    const int w = tid >> 5;                // 0..11
    const int g_rt  = w & 3;               // GEMM rowtile
    const int g_grp = w >> 2;              // GEMM col group (0..2)
    const int g_nt  = (g_grp == 0) ? 6 : 5;

    unsigned* af_s = (unsigned*)xr_s;      // A-fragment buffer (hi 16KB + lo 16KB)

    // ---- load packed src indices ----
    for (int e = tid; e < EE; e += NT) esrc_s[e] = (unsigned char)g_srcp[e];

    // ---- h = T0 = (attr_emb + opt_emb[n, x]) * prior ----
    for (int idx = tid; idx < NN * DD; idx += NT) {
        const int n = idx >> 7, d = idx & 127;
        const int xv = x[b * NN + n];
        h_s[idx] = (attr_emb[idx] + opt_emb[(n * KK + xv) * DD + d]) * prior[n];
    }
    __syncthreads();

    for (int l = 0; l < LL; ++l) {
        // ---- convert h to fp16 hi/lo fragments (into xr_s) ----
        convert_A(h_s, af_s, tid);
        __syncthreads();

        // ---- xl = h@Wl + bl ; xr = h@Wr + br  (direct-LDG B, no staging) ----
        {
            float c[6][4];
            cinit(c, bl + l * DD, g_grp, lane, g_nt);
            gemm_ld(c, af_s, g_Bpack + (2 * l) * 16384, lane, g_rt, g_grp, g_nt);
            cstore(c, xl_s, g_rt, g_grp, lane, g_nt);

            cinit(c, br + l * DD, g_grp, lane, g_nt);
            gemm_ld(c, af_s, g_Bpack + (2 * l + 1) * 16384, lane, g_rt, g_grp, g_nt);
            __syncthreads();                     // all warps done reading A-frags
            cstore(c, xr_s, g_rt, g_grp, lane, g_nt);   // overwrites af region
        }
        __syncthreads();                         // publish xl, xr

        // ======== fused edge phase: alpha -> softmax -> aggregate+LN ========
        // warp w owns nodes {w, w+12, ...}; all cross-lane data stays in-warp.
        float* alpha_s = un_s;                   // [H][EE]
        const int head = lane >> 3;
        const int el   = lane & 7;

        // ---- alpha ----
        {
            const float4 We4  = *(const float4*)(We  + l * DD + lane * 4);
            const float4 att4 = *(const float4*)(att + l * DD + lane * 4);
            for (int n = w; n < NN; n += NW) {
                const float4 xr4 = *(const float4*)(xr_s + n * DD + lane * 4);
                const int e0 = g_off[n], e1 = g_off[n + 1];
#pragma unroll 2
                for (int i = e0; i < e1; ++i) {
                    const int s = esrc_s[i];
                    const float eav = g_eap[i];
                    const float4 xl4 = *(const float4*)(xl_s + s * DD + lane * 4);
                    float z0 = xl4.x + xr4.x + eav * We4.x;
                    float z1 = xl4.y + xr4.y + eav * We4.y;
                    float z2 = xl4.z + xr4.z + eav * We4.z;
                    float z3 = xl4.w + xr4.w + eav * We4.w;
                    z0 = z0 > 0.f ? z0 : 0.2f * z0;
                    z1 = z1 > 0.f ? z1 : 0.2f * z1;
                    z2 = z2 > 0.f ? z2 : 0.2f * z2;
                    z3 = z3 > 0.f ? z3 : 0.2f * z3;
                    float p = z0 * att4.x + z1 * att4.y + z2 * att4.z + z3 * att4.w;
                    p += __shfl_xor_sync(0xffffffffu, p, 1);
                    p += __shfl_xor_sync(0xffffffffu, p, 2);
                    p += __shfl_xor_sync(0xffffffffu, p, 4);
                    if (el == 0) alpha_s[head * EE + i] = p;
                }
            }
        }
        __syncwarp();

        // ---- softmax per node (own nodes only) ----
        {
            float* a = alpha_s + head * EE;
            for (int n = w; n < NN; n += NW) {
                const int e0 = g_off[n], e1 = g_off[n + 1];
                float m = -INFINITY;
                for (int i = e0 + el; i < e1; i += 8) m = fmaxf(m, a[i]);
                m = fmaxf(m, __shfl_xor_sync(0xffffffffu, m, 1));
                m = fmaxf(m, __shfl_xor_sync(0xffffffffu, m, 2));
                m = fmaxf(m, __shfl_xor_sync(0xffffffffu, m, 4));
                float s = 0.f;
                for (int i = e0 + el; i < e1; i += 8) {
                    const float ex = __expf(a[i] - m);
                    a[i] = ex;
                    s += ex;
                }
                s += __shfl_xor_sync(0xffffffffu, s, 1);
                s += __shfl_xor_sync(0xffffffffu, s, 2);
                s += __shfl_xor_sync(0xffffffffu, s, 4);
                const float inv = 1.f / s;
                for (int i = e0 + el; i < e1; i += 8) a[i] *= inv;
            }
        }
        __syncwarp();

        // ---- aggregate (row in regs) + LN + h update ----
        {
            const float4 cb4 = *(const float4*)(conv_bias + l * DD + lane * 4);
            const float4 lg4 = *(const float4*)(ln_g + l * DD + lane * 4);
            const float4 lb4 = *(const float4*)(ln_b + l * DD + lane * 4);
            const float* a = alpha_s + head * EE;
            for (int n = w; n < NN; n += NW) {
                const int e0 = g_off[n], e1 = g_off[n + 1];
                float v0 = 0.f, v1 = 0.f, v2 = 0.f, v3 = 0.f;
#pragma unroll 2
                for (int i = e0; i < e1; ++i) {
                    const float av = a[i];
                    const float4 xl4 = *(const float4*)(xl_s + (int)esrc_s[i] * DD + lane * 4);
                    v0 = fmaf(xl4.x, av, v0);
                    v1 = fmaf(xl4.y, av, v1);
                    v2 = fmaf(xl4.z, av, v2);
                    v3 = fmaf(xl4.w, av, v3);
                }
                v0 += cb4.x; v1 += cb4.y; v2 += cb4.z; v3 += cb4.w;
                float sum = v0 + v1 + v2 + v3;
                float sq  = v0*v0 + v1*v1 + v2*v2 + v3*v3;
#pragma unroll
                for (int o = 16; o; o >>= 1) {
                    sum += __shfl_xor_sync(0xffffffffu, sum, o);
                    sq  += __shfl_xor_sync(0xffffffffu, sq, o);
                }
                const float mu = sum * (1.f / DD);
                const float var = sq * (1.f / DD) - mu * mu;
                const float rstd = rsqrtf(var + 1e-5f);
                float t0v = (v0 - mu) * rstd * lg4.x + lb4.x;
                float t1v = (v1 - mu) * rstd * lg4.y + lb4.y;
                float t2v = (v2 - mu) * rstd * lg4.z + lb4.z;
                float t3v = (v3 - mu) * rstd * lg4.w + lb4.w;
                t0v = t0v > 0.f ? t0v : expm1f(t0v);
                t1v = t1v > 0.f ? t1v : expm1f(t1v);
                t2v = t2v > 0.f ? t2v : expm1f(t2v);
                t3v = t3v > 0.f ? t3v : expm1f(t3v);
                float4 hv = *(const float4*)(h_s + n * DD + lane * 4);
                hv.x += t0v; hv.y += t1v; hv.z += t2v; hv.w += t3v;
                *(float4*)(h_s + n * DD + lane * 4) = hv;
            }
        }
        __syncthreads();                   // publish h before next convert
    }

    // ---- MLP: q = relu([T0, h] @ W1 + b1) -> xl_s  (two K=128 passes) ----
    {
        float c[6][4];
        cinit(c, b1, g_grp, lane, g_nt);
        convert_T0(x, attr_emb, opt_emb, prior, b, af_s, tid);
        __syncthreads();
        gemm_ld(c, af_s, g_Bpack + 4 * 16384, lane, g_rt, g_grp, g_nt);
        __syncthreads();                   // all warps done with T0 frags
        convert_A(h_s, af_s, tid);
        __syncthreads();
        gemm_ld(c, af_s, g_Bpack + 5 * 16384, lane, g_rt, g_grp, g_nt);
        cstore_relu(c, xl_s, g_rt, g_grp, lane, g_nt);
    }
    __syncthreads();

    float* rel_s = un_s;          // [0..63], relsum at [64], partials at [128..512)

    // ---- rel[n] = sigmoid(q[n].W2 + b2)   (warp per node) ----
    {
        const long long OR = (long long)NB * DD;
        const float4 w24 = *(const float4*)(W2 + lane * 4);
        for (int n = w; n < NN; n += NW) {
            const float4 qv = *(const float4*)(xl_s + n * DD + lane * 4);
            float p = qv.x * w24.x + qv.y * w24.y + qv.z * w24.z + qv.w * w24.w;
#pragma unroll
            for (int o = 16; o; o >>= 1) p += __shfl_xor_sync(0xffffffffu, p, o);
            if (lane == 0) {
                const float r = 1.f / (1.f + expf(-(p + b2[0])));
                rel_s[n] = r;
                out[OR + (long long)b * NN + n] = r;
            }
        }
    }
    __syncthreads();

    // ---- rel sum (warp 0) ----
    if (w == 0) {
        float v = rel_s[lane] + rel_s[lane + 32];
#pragma unroll
        for (int o = 16; o; o >>= 1) v += __shfl_xor_sync(0xffffffffu, v, o);
        if (lane == 0) rel_s[64] = v;
    }

    // ---- f_scale partials (3-way) ----
    {
        const int d = tid & 127;
        const int q = tid >> 7;            // 0..2
        float acc = 0.f;
        for (int n = q; n < NN; n += 3)
            acc = fmaf(h_s[n * DD + d], rel_s[n], acc);
        un_s[128 + q * DD + d] = acc;
    }

    // ---- hat_T output: [T0 (recomputed), h] ----
    {
        const long long OH = (long long)NB * DD + (long long)NB * NN;
        for (int idx = tid; idx < NN * DD; idx += NT) {
            const int n = idx >> 7, d = idx & 127;
            const int xv = x[b * NN + n];
            const float t0 = (attr_emb[idx] + opt_emb[(n * KK + xv) * DD + d]) * prior[n];
            const long long base = OH + ((long long)b * NN + n) * (2 * DD);
            out[base + d] = t0;
            out[base + DD + d] = h_s[idx];
        }
    }
    __syncthreads();

    if (tid < DD) {
        const float num = un_s[128 + tid] + un_s[256 + tid] + un_s[384 + tid];
        out[(long long)b * DD + tid] = num / (rel_s[64] + 1e-8f);
    }
}

extern "C" void kernel_launch(void* const* d_in, const int* in_sizes, int n_in,
                              void* d_out, int out_size) {
    const int*   x         = (const int*)d_in[0];
    const int*   ei        = (const int*)d_in[1];
    const float* ea        = (const float*)d_in[2];
    const float* attr_emb  = (const float*)d_in[3];
    const float* opt_emb   = (const float*)d_in[4];
    const float* prior     = (const float*)d_in[5];
    const float* Wl        = (const float*)d_in[6];
    const float* bl        = (const float*)d_in[7];
    const float* Wr        = (const float*)d_in[8];
    const float* br        = (const float*)d_in[9];
    const float* We        = (const float*)d_in[10];
    const float* att       = (const float*)d_in[11];
    const float* conv_bias = (const float*)d_in[12];
    const float* ln_g      = (const float*)d_in[13];
    const float* ln_b      = (const float*)d_in[14];
    const float* W1        = (const float*)d_in[15];
    const float* b1        = (const float*)d_in[16];
    const float* W2        = (const float*)d_in[17];
    const float* b2        = (const float*)d_in[18];
    float* out = (float*)d_out;

    const size_t smem = 3 * NN * DD * sizeof(float) + HH * EE * sizeof(float) + EE;
    cudaFuncSetAttribute(gat_kernel, cudaFuncAttributeMaxDynamicSharedMemorySize, (int)smem);

    setup_kernel<<<7, EE>>>(ei, ea, Wl, Wr, W1);
    gat_kernel<<<NB, NT, smem>>>(x, attr_emb, opt_emb, prior,
                                 bl, br, We, att, conv_bias,
                                 ln_g, ln_b, b1, W2, b2, out);
}

// round 14
// speedup vs baseline: 2.6973x; 1.0861x over previous
#include <cuda_runtime.h>
#include <cuda_bf16.h>
#include <cuda_fp16.h>
#include <math.h>

#define NB 1024   // batches
#define NN 64     // nodes
#define DD 128    // feature dim
#define EE 1024   // edges
#define HH 4      // heads
#define KK 5
#define LL 2
#define NT 512    // threads per CTA
#define NW 16     // warps per CTA

// Edge data sorted by dst (CSR order), built once per launch
__device__ int   g_off[NN + 1];
__device__ int   g_srcp[EE];
__device__ float g_eap[EE];

// W matrices as fp16 hi/lo packed in m16n8k16 B-fragment order:
// mat m: slot s = (ks*16 + ct)*32 + lane; u32[4] = {bhi0, bhi1, blo0, blo1}
// mats: 0=Wl0 1=Wr0 2=Wl1 3=Wr1 4=W1[0:128] 5=W1[128:256]
__device__ unsigned g_Bpack[6 * 16384];

__device__ __forceinline__ unsigned packh2(__half a, __half b) {
    __half2 h; h.x = a; h.y = b;
    return *(const unsigned*)&h;
}

// Merged setup: block 0 = CSR build (1024 threads), blocks 1..6 = W packing.
__global__ __launch_bounds__(EE) void setup_kernel(const int* __restrict__ ei,
                                                   const float* __restrict__ ea,
                                                   const float* __restrict__ Wl,
                                                   const float* __restrict__ Wr,
                                                   const float* __restrict__ W1) {
    if (blockIdx.x == 0) {
        __shared__ int dstS[EE];
        __shared__ int degS[NN];
        __shared__ int offS[NN + 1];
        const int e = threadIdx.x;
        if (e < NN) degS[e] = 0;
        __syncthreads();
        const int d = ei[EE + e];
        dstS[e] = d;
        atomicAdd(&degS[d], 1);
        __syncthreads();
        if (e == 0) {
            int s = 0;
            for (int i = 0; i < NN; ++i) { offS[i] = s; s += degS[i]; }
            offS[NN] = s;
        }
        __syncthreads();
        int rank = 0;
        for (int j = 0; j < e; ++j) rank += (dstS[j] == d);
        const int p = offS[d] + rank;
        g_srcp[p] = ei[e];
        g_eap[p]  = ea[e];
        if (e <= NN) g_off[e] = offS[e];
    } else {
        const int m = blockIdx.x - 1;    // 0..5
        const float* src = (m == 0) ? Wl : (m == 1) ? Wr : (m == 2) ? Wl + 16384
                         : (m == 3) ? Wr + 16384 : (m == 4) ? W1 : W1 + 16384;
        for (int s = threadIdx.x; s < 4096; s += blockDim.x) {
            const int lane = s & 31, ct = (s >> 5) & 15, ks = s >> 9;
            const int n  = ct * 8 + (lane >> 2);
            const int k0 = ks * 16 + (lane & 3) * 2;
            float v[4];
            v[0] = src[(k0)     * DD + n];
            v[1] = src[(k0 + 1) * DD + n];
            v[2] = src[(k0 + 8) * DD + n];
            v[3] = src[(k0 + 9) * DD + n];
            __half h[4], l[4];
#pragma unroll
            for (int i = 0; i < 4; ++i) {
                h[i] = __float2half_rn(v[i]);
                l[i] = __float2half_rn(v[i] - __half2float(h[i]));
            }
            unsigned* o = g_Bpack + m * 16384 + s * 4;
            o[0] = packh2(h[0], h[1]);
            o[1] = packh2(h[2], h[3]);
            o[2] = packh2(l[0], l[1]);
            o[3] = packh2(l[2], l[3]);
        }
    }
}

__device__ __forceinline__ void mma_f16(float c[4], const unsigned a[4],
                                        unsigned b0, unsigned b1) {
    asm("mma.sync.aligned.m16n8k16.row.col.f32.f16.f16.f32 "
        "{%0,%1,%2,%3},{%4,%5,%6,%7},{%8,%9},{%0,%1,%2,%3};"
        : "+f"(c[0]), "+f"(c[1]), "+f"(c[2]), "+f"(c[3])
        : "r"(a[0]), "r"(a[1]), "r"(a[2]), "r"(a[3]), "r"(b0), "r"(b1));
}

// Convert fp32 A (64x128 row-major, smem) into fragment-ordered fp16 hi/lo.
__device__ __forceinline__ void convert_A(const float* __restrict__ A,
                                          unsigned* __restrict__ dst, int tid) {
    for (int s = tid; s < 4096; s += NT) {
        const int j = s & 3, lane = (s >> 2) & 31, ks = (s >> 7) & 7, rt = s >> 10;
        const int row = rt * 16 + (lane >> 2) + ((j & 1) << 3);
        const int col = ks * 16 + (lane & 3) * 2 + ((j & 2) << 2);
        const float v0 = A[row * DD + col], v1 = A[row * DD + col + 1];
        const __half h0 = __float2half_rn(v0), h1 = __float2half_rn(v1);
        const __half l0 = __float2half_rn(v0 - __half2float(h0));
        const __half l1 = __float2half_rn(v1 - __half2float(h1));
        dst[s]        = packh2(h0, h1);
        dst[4096 + s] = packh2(l0, l1);
    }
}

__device__ __forceinline__ void convert_T0(const int* __restrict__ x,
                                           const float* __restrict__ attr_emb,
                                           const float* __restrict__ opt_emb,
                                           const float* __restrict__ prior,
                                           int b, unsigned* __restrict__ dst, int tid) {
    for (int s = tid; s < 4096; s += NT) {
        const int j = s & 3, lane = (s >> 2) & 31, ks = (s >> 7) & 7, rt = s >> 10;
        const int row = rt * 16 + (lane >> 2) + ((j & 1) << 3);
        const int col = ks * 16 + (lane & 3) * 2 + ((j & 2) << 2);
        const int xv = x[b * NN + row];
        const float pr = prior[row];
        const float v0 = (attr_emb[row * DD + col] + opt_emb[(row * KK + xv) * DD + col]) * pr;
        const float v1 = (attr_emb[row * DD + col + 1] + opt_emb[(row * KK + xv) * DD + col + 1]) * pr;
        const __half h0 = __float2half_rn(v0), h1 = __float2half_rn(v1);
        const __half l0 = __float2half_rn(v0 - __half2float(h0));
        const __half l1 = __float2half_rn(v1 - __half2float(h1));
        dst[s]        = packh2(h0, h1);
        dst[4096 + s] = packh2(l0, l1);
    }
}

// 64x128 @ 128x128 accumulate, B read DIRECTLY from global (L1-resident).
// Warp (rt, cg): rows rt*16..+16, coltiles ct = cg*4 + j, j<4.
__device__ __forceinline__ void gemm_ld(float c[4][4], const unsigned* __restrict__ Af,
                                        const unsigned* __restrict__ Bp,
                                        int lane, int rt, int cg) {
#pragma unroll 2
    for (int ks = 0; ks < 8; ++ks) {
        unsigned ah[4], al[4];
        *(uint4*)ah = *(const uint4*)&Af[((rt * 8 + ks) * 32 + lane) * 4];
        *(uint4*)al = *(const uint4*)&Af[4096 + ((rt * 8 + ks) * 32 + lane) * 4];
        uint4 B[4];
#pragma unroll
        for (int j = 0; j < 4; ++j)
            B[j] = *(const uint4*)&Bp[((ks * 16 + cg * 4 + j) * 32 + lane) * 4];
#pragma unroll
        for (int j = 0; j < 4; ++j) mma_f16(c[j], ah, B[j].x, B[j].y);
#pragma unroll
        for (int j = 0; j < 4; ++j) mma_f16(c[j], ah, B[j].z, B[j].w);
#pragma unroll
        for (int j = 0; j < 4; ++j) mma_f16(c[j], al, B[j].x, B[j].y);
    }
}

__device__ __forceinline__ void cinit(float c[4][4], const float* __restrict__ bias,
                                      int cg, int lane) {
#pragma unroll
    for (int j = 0; j < 4; ++j) {
        const int col = (cg * 4 + j) * 8 + (lane & 3) * 2;
        c[j][0] = bias[col];
        c[j][1] = bias[col + 1];
        c[j][2] = c[j][0];
        c[j][3] = c[j][1];
    }
}

__device__ __forceinline__ void cstore(const float c[4][4], float* __restrict__ dst,
                                       int rt, int cg, int lane) {
    const int row = rt * 16 + (lane >> 2);
#pragma unroll
    for (int j = 0; j < 4; ++j) {
        const int col = (cg * 4 + j) * 8 + (lane & 3) * 2;
        *(float2*)(dst + row * DD + col)       = make_float2(c[j][0], c[j][1]);
        *(float2*)(dst + (row + 8) * DD + col) = make_float2(c[j][2], c[j][3]);
    }
}

__device__ __forceinline__ void cstore_relu(const float c[4][4], float* __restrict__ dst,
                                            int rt, int cg, int lane) {
    const int row = rt * 16 + (lane >> 2);
#pragma unroll
    for (int j = 0; j < 4; ++j) {
        const int col = (cg * 4 + j) * 8 + (lane & 3) * 2;
        *(float2*)(dst + row * DD + col) =
            make_float2(fmaxf(c[j][0], 0.f), fmaxf(c[j][1], 0.f));
        *(float2*)(dst + (row + 8) * DD + col) =
            make_float2(fmaxf(c[j][2], 0.f), fmaxf(c[j][3], 0.f));
    }
}

__global__ __launch_bounds__(NT, 2) void gat_kernel(
    const int* __restrict__ x,
    const float* __restrict__ attr_emb, const float* __restrict__ opt_emb,
    const float* __restrict__ prior,
    const float* __restrict__ bl, const float* __restrict__ br,
    const float* __restrict__ We, const float* __restrict__ att,
    const float* __restrict__ conv_bias, const float* __restrict__ ln_g,
    const float* __restrict__ ln_b,
    const float* __restrict__ b1,
    const float* __restrict__ W2, const float* __restrict__ b2,
    float* __restrict__ out) {
    extern __shared__ float sm[];
    float* h_s   = sm;                     // 8192 floats (h; starts as T0)
    float* xl_s  = h_s + NN * DD;          // 8192
    float* xr_s  = xl_s + NN * DD;         // 8192 (A-fp16 frags / xr)
    float* un_s  = xr_s + NN * DD;         // 4096: union{ alpha[H][EE] | epilogue }
    unsigned char* esrc_s = (unsigned char*)(un_s + HH * EE);  // 1024 B

    const int b = blockIdx.x;
    const int tid = threadIdx.x;
    const int lane = tid & 31;
    const int w = tid >> 5;                // 0..15
    const int g_rt = w & 3;                // GEMM rowtile
    const int g_cg = w >> 2;               // GEMM col group (0..3)

    unsigned* af_s = (unsigned*)xr_s;      // A-fragment buffer (hi 16KB + lo 16KB)

    // ---- load packed src indices ----
    for (int e = tid; e < EE; e += NT) esrc_s[e] = (unsigned char)g_srcp[e];

    // ---- h = T0 = (attr_emb + opt_emb[n, x]) * prior  (float4) ----
    for (int idx = tid; idx < NN * DD / 4; idx += NT) {
        const int n = idx >> 5, d4 = (idx & 31) * 4;
        const int xv = x[b * NN + n];
        const float pr = prior[n];
        const float4 a4 = *(const float4*)(attr_emb + n * DD + d4);
        const float4 o4 = *(const float4*)(opt_emb + (n * KK + xv) * DD + d4);
        float4 h4;
        h4.x = (a4.x + o4.x) * pr;
        h4.y = (a4.y + o4.y) * pr;
        h4.z = (a4.z + o4.z) * pr;
        h4.w = (a4.w + o4.w) * pr;
        *(float4*)(h_s + n * DD + d4) = h4;
    }
    __syncthreads();

    for (int l = 0; l < LL; ++l) {
        // ---- convert h to fp16 hi/lo fragments (into xr_s) ----
        convert_A(h_s, af_s, tid);
        __syncthreads();

        // ---- xl = h@Wl + bl ; xr = h@Wr + br  (direct-LDG B, no staging) ----
        {
            float c[4][4];
            cinit(c, bl + l * DD, g_cg, lane);
            gemm_ld(c, af_s, g_Bpack + (2 * l) * 16384, lane, g_rt, g_cg);
            cstore(c, xl_s, g_rt, g_cg, lane);

            cinit(c, br + l * DD, g_cg, lane);
            gemm_ld(c, af_s, g_Bpack + (2 * l + 1) * 16384, lane, g_rt, g_cg);
            __syncthreads();                     // all warps done reading A-frags
            cstore(c, xr_s, g_rt, g_cg, lane);   // overwrites af region
        }
        __syncthreads();                         // publish xl, xr

        // ======== fused edge phase: alpha -> softmax -> aggregate+LN ========
        // warp w owns nodes {w, w+16, ...}; all cross-lane data stays in-warp.
        float* alpha_s = un_s;                   // [H][EE]
        const int head = lane >> 3;
        const int el   = lane & 7;

        // ---- alpha ----
        {
            const float4 We4  = *(const float4*)(We  + l * DD + lane * 4);
            const float4 att4 = *(const float4*)(att + l * DD + lane * 4);
            for (int n = w; n < NN; n += NW) {
                const float4 xr4 = *(const float4*)(xr_s + n * DD + lane * 4);
                const int e0 = g_off[n], e1 = g_off[n + 1];
#pragma unroll 2
                for (int i = e0; i < e1; ++i) {
                    const int s = esrc_s[i];
                    const float eav = g_eap[i];
                    const float4 xl4 = *(const float4*)(xl_s + s * DD + lane * 4);
                    float z0 = xl4.x + xr4.x + eav * We4.x;
                    float z1 = xl4.y + xr4.y + eav * We4.y;
                    float z2 = xl4.z + xr4.z + eav * We4.z;
                    float z3 = xl4.w + xr4.w + eav * We4.w;
                    z0 = z0 > 0.f ? z0 : 0.2f * z0;
                    z1 = z1 > 0.f ? z1 : 0.2f * z1;
                    z2 = z2 > 0.f ? z2 : 0.2f * z2;
                    z3 = z3 > 0.f ? z3 : 0.2f * z3;
                    float p = z0 * att4.x + z1 * att4.y + z2 * att4.z + z3 * att4.w;
                    p += __shfl_xor_sync(0xffffffffu, p, 1);
                    p += __shfl_xor_sync(0xffffffffu, p, 2);
                    p += __shfl_xor_sync(0xffffffffu, p, 4);
                    if (el == 0) alpha_s[head * EE + i] = p;
                }
            }
        }
        __syncwarp();

        // ---- softmax per node (own nodes only) ----
        {
            float* a = alpha_s + head * EE;
            for (int n = w; n < NN; n += NW) {
                const int e0 = g_off[n], e1 = g_off[n + 1];
                float m = -INFINITY;
                for (int i = e0 + el; i < e1; i += 8) m = fmaxf(m, a[i]);
                m = fmaxf(m, __shfl_xor_sync(0xffffffffu, m, 1));
                m = fmaxf(m, __shfl_xor_sync(0xffffffffu, m, 2));
                m = fmaxf(m, __shfl_xor_sync(0xffffffffu, m, 4));
                float s = 0.f;
                for (int i = e0 + el; i < e1; i += 8) {
                    const float ex = __expf(a[i] - m);
                    a[i] = ex;
                    s += ex;
                }
                s += __shfl_xor_sync(0xffffffffu, s, 1);
                s += __shfl_xor_sync(0xffffffffu, s, 2);
                s += __shfl_xor_sync(0xffffffffu, s, 4);
                const float inv = 1.f / s;
                for (int i = e0 + el; i < e1; i += 8) a[i] *= inv;
            }
        }
        __syncwarp();

        // ---- aggregate (row in regs) + LN + h update ----
        {
            const float4 cb4 = *(const float4*)(conv_bias + l * DD + lane * 4);
            const float4 lg4 = *(const float4*)(ln_g + l * DD + lane * 4);
            const float4 lb4 = *(const float4*)(ln_b + l * DD + lane * 4);
            const float* a = alpha_s + head * EE;
            for (int n = w; n < NN; n += NW) {
                const int e0 = g_off[n], e1 = g_off[n + 1];
                float v0 = 0.f, v1 = 0.f, v2 = 0.f, v3 = 0.f;
#pragma unroll 2
                for (int i = e0; i < e1; ++i) {
                    const float av = a[i];
                    const float4 xl4 = *(const float4*)(xl_s + (int)esrc_s[i] * DD + lane * 4);
                    v0 = fmaf(xl4.x, av, v0);
                    v1 = fmaf(xl4.y, av, v1);
                    v2 = fmaf(xl4.z, av, v2);
                    v3 = fmaf(xl4.w, av, v3);
                }
                v0 += cb4.x; v1 += cb4.y; v2 += cb4.z; v3 += cb4.w;
                float sum = v0 + v1 + v2 + v3;
                float sq  = v0*v0 + v1*v1 + v2*v2 + v3*v3;
#pragma unroll
                for (int o = 16; o; o >>= 1) {
                    sum += __shfl_xor_sync(0xffffffffu, sum, o);
                    sq  += __shfl_xor_sync(0xffffffffu, sq, o);
                }
                const float mu = sum * (1.f / DD);
                const float var = sq * (1.f / DD) - mu * mu;
                const float rstd = rsqrtf(var + 1e-5f);
                float t0v = (v0 - mu) * rstd * lg4.x + lb4.x;
                float t1v = (v1 - mu) * rstd * lg4.y + lb4.y;
                float t2v = (v2 - mu) * rstd * lg4.z + lb4.z;
                float t3v = (v3 - mu) * rstd * lg4.w + lb4.w;
                t0v = t0v > 0.f ? t0v : expm1f(t0v);
                t1v = t1v > 0.f ? t1v : expm1f(t1v);
                t2v = t2v > 0.f ? t2v : expm1f(t2v);
                t3v = t3v > 0.f ? t3v : expm1f(t3v);
                float4 hv = *(const float4*)(h_s + n * DD + lane * 4);
                hv.x += t0v; hv.y += t1v; hv.z += t2v; hv.w += t3v;
                *(float4*)(h_s + n * DD + lane * 4) = hv;
            }
        }
        __syncthreads();                   // publish h before next convert
    }

    // ---- MLP: q = relu([T0, h] @ W1 + b1) -> xl_s  (two K=128 passes) ----
    {
        float c[4][4];
        cinit(c, b1, g_cg, lane);
        convert_T0(x, attr_emb, opt_emb, prior, b, af_s, tid);
        __syncthreads();
        gemm_ld(c, af_s, g_Bpack + 4 * 16384, lane, g_rt, g_cg);
        __syncthreads();                   // all warps done with T0 frags
        convert_A(h_s, af_s, tid);
        __syncthreads();
        gemm_ld(c, af_s, g_Bpack + 5 * 16384, lane, g_rt, g_cg);
        cstore_relu(c, xl_s, g_rt, g_cg, lane);
    }
    __syncthreads();

    float* rel_s = un_s;          // [0..63], relsum at [64], partials at [128..640)

    // ---- rel[n] = sigmoid(q[n].W2 + b2)   (warp per node) ----
    {
        const long long OR = (long long)NB * DD;
        const float4 w24 = *(const float4*)(W2 + lane * 4);
        for (int n = w; n < NN; n += NW) {
            const float4 qv = *(const float4*)(xl_s + n * DD + lane * 4);
            float p = qv.x * w24.x + qv.y * w24.y + qv.z * w24.z + qv.w * w24.w;
#pragma unroll
            for (int o = 16; o; o >>= 1) p += __shfl_xor_sync(0xffffffffu, p, o);
            if (lane == 0) {
                const float r = 1.f / (1.f + expf(-(p + b2[0])));
                rel_s[n] = r;
                out[OR + (long long)b * NN + n] = r;
            }
        }
    }
    __syncthreads();

    // ---- rel sum (warp 0) ----
    if (w == 0) {
        float v = rel_s[lane] + rel_s[lane + 32];
#pragma unroll
        for (int o = 16; o; o >>= 1) v += __shfl_xor_sync(0xffffffffu, v, o);
        if (lane == 0) rel_s[64] = v;
    }

    // ---- f_scale partials (4-way) ----
    {
        const int d = tid & 127;
        const int q = tid >> 7;            // 0..3
        float acc = 0.f;
        for (int n = q; n < NN; n += 4)
            acc = fmaf(h_s[n * DD + d], rel_s[n], acc);
        un_s[128 + q * DD + d] = acc;
    }

    // ---- hat_T output: [T0 (recomputed), h]  (float4) ----
    {
        const long long OH = (long long)NB * DD + (long long)NB * NN;
        for (int idx = tid; idx < NN * DD / 4; idx += NT) {
            const int n = idx >> 5, d4 = (idx & 31) * 4;
            const int xv = x[b * NN + n];
            const float pr = prior[n];
            const float4 a4 = *(const float4*)(attr_emb + n * DD + d4);
            const float4 o4 = *(const float4*)(opt_emb + (n * KK + xv) * DD + d4);
            float4 t4;
            t4.x = (a4.x + o4.x) * pr;
            t4.y = (a4.y + o4.y) * pr;
            t4.z = (a4.z + o4.z) * pr;
            t4.w = (a4.w + o4.w) * pr;
            const long long base = OH + ((long long)b * NN + n) * (2 * DD);
            *(float4*)(out + base + d4) = t4;
            *(float4*)(out + base + DD + d4) = *(const float4*)(h_s + n * DD + d4);
        }
    }
    __syncthreads();

    if (tid < DD) {
        const float num = un_s[128 + tid] + un_s[256 + tid] +
                          un_s[384 + tid] + un_s[512 + tid];
        out[(long long)b * DD + tid] = num / (rel_s[64] + 1e-8f);
    }
}

extern "C" void kernel_launch(void* const* d_in, const int* in_sizes, int n_in,
                              void* d_out, int out_size) {
    const int*   x         = (const int*)d_in[0];
    const int*   ei        = (const int*)d_in[1];
    const float* ea        = (const float*)d_in[2];
    const float* attr_emb  = (const float*)d_in[3];
    const float* opt_emb   = (const float*)d_in[4];
    const float* prior     = (const float*)d_in[5];
    const float* Wl        = (const float*)d_in[6];
    const float* bl        = (const float*)d_in[7];
    const float* Wr        = (const float*)d_in[8];
    const float* br        = (const float*)d_in[9];
    const float* We        = (const float*)d_in[10];
    const float* att       = (const float*)d_in[11];
    const float* conv_bias = (const float*)d_in[12];
    const float* ln_g      = (const float*)d_in[13];
    const float* ln_b      = (const float*)d_in[14];
    const float* W1        = (const float*)d_in[15];
    const float* b1        = (const float*)d_in[16];
    const float* W2        = (const float*)d_in[17];
    const float* b2        = (const float*)d_in[18];
    float* out = (float*)d_out;

    const size_t smem = 3 * NN * DD * sizeof(float) + HH * EE * sizeof(float) + EE;
    cudaFuncSetAttribute(gat_kernel, cudaFuncAttributeMaxDynamicSharedMemorySize, (int)smem);

    setup_kernel<<<7, EE>>>(ei, ea, Wl, Wr, W1);
    gat_kernel<<<NB, NT, smem>>>(x, attr_emb, opt_emb, prior,
                                 bl, br, We, att, conv_bias,
                                 ln_g, ln_b, b1, W2, b2, out);
}

// round 15
// speedup vs baseline: 3.1516x; 1.1684x over previous
#include <cuda_runtime.h>
#include <cuda_bf16.h>
#include <cuda_fp16.h>
#include <math.h>

#define NB 1024   // batches
#define NN 64     // nodes
#define DD 128    // feature dim
#define EE 1024   // edges
#define HH 4      // heads
#define KK 5
#define LL 2
#define NT 512    // threads per CTA
#define NW 16     // warps per CTA

// Edge data sorted by dst (CSR order), built once per launch
__device__ int   g_off[NN + 1];
__device__ int   g_srcp[EE];
__device__ float g_eap[EE];

// W matrices as fp16 hi/lo packed in m16n8k16 B-fragment order:
// mat m: slot s = (ks*16 + ct)*32 + lane; u32[4] = {bhi0, bhi1, blo0, blo1}
// mats: 0=Wl0 1=Wr0 2=Wl1 3=Wr1 4=W1[0:128] 5=W1[128:256]
__device__ unsigned g_Bpack[6 * 16384];

__device__ __forceinline__ unsigned packh2(__half a, __half b) {
    __half2 h; h.x = a; h.y = b;
    return *(const unsigned*)&h;
}

// Merged setup: block 0 = CSR build (1024 threads), blocks 1..6 = W packing.
__global__ __launch_bounds__(EE) void setup_kernel(const int* __restrict__ ei,
                                                   const float* __restrict__ ea,
                                                   const float* __restrict__ Wl,
                                                   const float* __restrict__ Wr,
                                                   const float* __restrict__ W1) {
    if (blockIdx.x == 0) {
        __shared__ int dstS[EE];
        __shared__ int degS[NN];
        __shared__ int offS[NN + 1];
        const int e = threadIdx.x;
        if (e < NN) degS[e] = 0;
        __syncthreads();
        const int d = ei[EE + e];
        dstS[e] = d;
        atomicAdd(&degS[d], 1);
        __syncthreads();
        if (e == 0) {
            int s = 0;
            for (int i = 0; i < NN; ++i) { offS[i] = s; s += degS[i]; }
            offS[NN] = s;
        }
        __syncthreads();
        int rank = 0;
        for (int j = 0; j < e; ++j) rank += (dstS[j] == d);
        const int p = offS[d] + rank;
        g_srcp[p] = ei[e];
        g_eap[p]  = ea[e];
        if (e <= NN) g_off[e] = offS[e];
    } else {
        const int m = blockIdx.x - 1;    // 0..5
        const float* src = (m == 0) ? Wl : (m == 1) ? Wr : (m == 2) ? Wl + 16384
                         : (m == 3) ? Wr + 16384 : (m == 4) ? W1 : W1 + 16384;
        for (int s = threadIdx.x; s < 4096; s += blockDim.x) {
            const int lane = s & 31, ct = (s >> 5) & 15, ks = s >> 9;
            const int n  = ct * 8 + (lane >> 2);
            const int k0 = ks * 16 + (lane & 3) * 2;
            float v[4];
            v[0] = src[(k0)     * DD + n];
            v[1] = src[(k0 + 1) * DD + n];
            v[2] = src[(k0 + 8) * DD + n];
            v[3] = src[(k0 + 9) * DD + n];
            __half h[4], l[4];
#pragma unroll
            for (int i = 0; i < 4; ++i) {
                h[i] = __float2half_rn(v[i]);
                l[i] = __float2half_rn(v[i] - __half2float(h[i]));
            }
            unsigned* o = g_Bpack + m * 16384 + s * 4;
            o[0] = packh2(h[0], h[1]);
            o[1] = packh2(h[2], h[3]);
            o[2] = packh2(l[0], l[1]);
            o[3] = packh2(l[2], l[3]);
        }
    }
}

__device__ __forceinline__ void mma_f16(float c[4], const unsigned a[4],
                                        unsigned b0, unsigned b1) {
    asm("mma.sync.aligned.m16n8k16.row.col.f32.f16.f16.f32 "
        "{%0,%1,%2,%3},{%4,%5,%6,%7},{%8,%9},{%0,%1,%2,%3};"
        : "+f"(c[0]), "+f"(c[1]), "+f"(c[2]), "+f"(c[3])
        : "r"(a[0]), "r"(a[1]), "r"(a[2]), "r"(a[3]), "r"(b0), "r"(b1));
}

// Convert fp32 A (64x128 row-major, smem) into fragment-ordered fp16 hi/lo.
__device__ __forceinline__ void convert_A(const float* __restrict__ A,
                                          unsigned* __restrict__ dst, int tid) {
    for (int s = tid; s < 4096; s += NT) {
        const int j = s & 3, lane = (s >> 2) & 31, ks = (s >> 7) & 7, rt = s >> 10;
        const int row = rt * 16 + (lane >> 2) + ((j & 1) << 3);
        const int col = ks * 16 + (lane & 3) * 2 + ((j & 2) << 2);
        const float v0 = A[row * DD + col], v1 = A[row * DD + col + 1];
        const __half h0 = __float2half_rn(v0), h1 = __float2half_rn(v1);
        const __half l0 = __float2half_rn(v0 - __half2float(h0));
        const __half l1 = __float2half_rn(v1 - __half2float(h1));
        dst[s]        = packh2(h0, h1);
        dst[4096 + s] = packh2(l0, l1);
    }
}

__device__ __forceinline__ void convert_T0(const int* __restrict__ x,
                                           const float* __restrict__ attr_emb,
                                           const float* __restrict__ opt_emb,
                                           const float* __restrict__ prior,
                                           int b, unsigned* __restrict__ dst, int tid) {
    for (int s = tid; s < 4096; s += NT) {
        const int j = s & 3, lane = (s >> 2) & 31, ks = (s >> 7) & 7, rt = s >> 10;
        const int row = rt * 16 + (lane >> 2) + ((j & 1) << 3);
        const int col = ks * 16 + (lane & 3) * 2 + ((j & 2) << 2);
        const int xv = x[b * NN + row];
        const float pr = prior[row];
        const float v0 = (attr_emb[row * DD + col] + opt_emb[(row * KK + xv) * DD + col]) * pr;
        const float v1 = (attr_emb[row * DD + col + 1] + opt_emb[(row * KK + xv) * DD + col + 1]) * pr;
        const __half h0 = __float2half_rn(v0), h1 = __float2half_rn(v1);
        const __half l0 = __float2half_rn(v0 - __half2float(h0));
        const __half l1 = __float2half_rn(v1 - __half2float(h1));
        dst[s]        = packh2(h0, h1);
        dst[4096 + s] = packh2(l0, l1);
    }
}

// 64x128 @ 128x128 accumulate, B read DIRECTLY from global (L1-cached).
// Warp (rt, cg): rows rt*16..+16, coltiles ct = cg*4 + j, j<4.
__device__ __forceinline__ void gemm_ld(float c[4][4], const unsigned* __restrict__ Af,
                                        const unsigned* __restrict__ Bp,
                                        int lane, int rt, int cg) {
#pragma unroll 2
    for (int ks = 0; ks < 8; ++ks) {
        unsigned ah[4], al[4];
        *(uint4*)ah = *(const uint4*)&Af[((rt * 8 + ks) * 32 + lane) * 4];
        *(uint4*)al = *(const uint4*)&Af[4096 + ((rt * 8 + ks) * 32 + lane) * 4];
        uint4 B[4];
#pragma unroll
        for (int j = 0; j < 4; ++j)
            B[j] = *(const uint4*)&Bp[((ks * 16 + cg * 4 + j) * 32 + lane) * 4];
#pragma unroll
        for (int j = 0; j < 4; ++j) mma_f16(c[j], ah, B[j].x, B[j].y);
#pragma unroll
        for (int j = 0; j < 4; ++j) mma_f16(c[j], ah, B[j].z, B[j].w);
#pragma unroll
        for (int j = 0; j < 4; ++j) mma_f16(c[j], al, B[j].x, B[j].y);
    }
}

__device__ __forceinline__ void cinit(float c[4][4], const float* __restrict__ bias,
                                      int cg, int lane) {
#pragma unroll
    for (int j = 0; j < 4; ++j) {
        const int col = (cg * 4 + j) * 8 + (lane & 3) * 2;
        c[j][0] = bias[col];
        c[j][1] = bias[col + 1];
        c[j][2] = c[j][0];
        c[j][3] = c[j][1];
    }
}

__device__ __forceinline__ void cstore(const float c[4][4], float* __restrict__ dst,
                                       int rt, int cg, int lane) {
    const int row = rt * 16 + (lane >> 2);
#pragma unroll
    for (int j = 0; j < 4; ++j) {
        const int col = (cg * 4 + j) * 8 + (lane & 3) * 2;
        *(float2*)(dst + row * DD + col)       = make_float2(c[j][0], c[j][1]);
        *(float2*)(dst + (row + 8) * DD + col) = make_float2(c[j][2], c[j][3]);
    }
}

__device__ __forceinline__ void cstore_relu(const float c[4][4], float* __restrict__ dst,
                                            int rt, int cg, int lane) {
    const int row = rt * 16 + (lane >> 2);
#pragma unroll
    for (int j = 0; j < 4; ++j) {
        const int col = (cg * 4 + j) * 8 + (lane & 3) * 2;
        *(float2*)(dst + row * DD + col) =
            make_float2(fmaxf(c[j][0], 0.f), fmaxf(c[j][1], 0.f));
        *(float2*)(dst + (row + 8) * DD + col) =
            make_float2(fmaxf(c[j][2], 0.f), fmaxf(c[j][3], 0.f));
    }
}

__global__ __launch_bounds__(NT, 2) void gat_kernel(
    const int* __restrict__ x,
    const float* __restrict__ attr_emb, const float* __restrict__ opt_emb,
    const float* __restrict__ prior,
    const float* __restrict__ bl, const float* __restrict__ br,
    const float* __restrict__ We, const float* __restrict__ att,
    const float* __restrict__ conv_bias, const float* __restrict__ ln_g,
    const float* __restrict__ ln_b,
    const float* __restrict__ b1,
    const float* __restrict__ W2, const float* __restrict__ b2,
    float* __restrict__ out) {
    extern __shared__ float sm[];
    float* h_s   = sm;                     // 8192 floats (h; starts as T0)
    float* xl_s  = h_s + NN * DD;          // 8192
    float* xr_s  = xl_s + NN * DD;         // 8192 (A-fp16 frags / xr)
    float* ep_s  = xr_s + NN * DD;         // 768: rel[0..64] + partials [128..640)
    unsigned char* esrc_s = (unsigned char*)(ep_s + 768);  // 1024 B
    // total = 3*32768 + 3072 + 1024 = 102400 B -> L1D carveout ~25KB at 2 CTAs

    const int b = blockIdx.x;
    const int tid = threadIdx.x;
    const int lane = tid & 31;
    const int w = tid >> 5;                // 0..15
    const int g_rt = w & 3;                // GEMM rowtile
    const int g_cg = w >> 2;               // GEMM col group (0..3)

    unsigned* af_s = (unsigned*)xr_s;      // A-fragment buffer (hi 16KB + lo 16KB)

    // ---- load packed src indices ----
    for (int e = tid; e < EE; e += NT) esrc_s[e] = (unsigned char)g_srcp[e];

    // ---- h = T0 = (attr_emb + opt_emb[n, x]) * prior  (float4) ----
    for (int idx = tid; idx < NN * DD / 4; idx += NT) {
        const int n = idx >> 5, d4 = (idx & 31) * 4;
        const int xv = x[b * NN + n];
        const float pr = prior[n];
        const float4 a4 = *(const float4*)(attr_emb + n * DD + d4);
        const float4 o4 = *(const float4*)(opt_emb + (n * KK + xv) * DD + d4);
        float4 h4;
        h4.x = (a4.x + o4.x) * pr;
        h4.y = (a4.y + o4.y) * pr;
        h4.z = (a4.z + o4.z) * pr;
        h4.w = (a4.w + o4.w) * pr;
        *(float4*)(h_s + n * DD + d4) = h4;
    }
    __syncthreads();

    for (int l = 0; l < LL; ++l) {
        // ---- convert h to fp16 hi/lo fragments (into xr_s) ----
        convert_A(h_s, af_s, tid);
        __syncthreads();

        // ---- xl = h@Wl + bl ; xr = h@Wr + br  (direct-LDG B) ----
        {
            float c[4][4];
            cinit(c, bl + l * DD, g_cg, lane);
            gemm_ld(c, af_s, g_Bpack + (2 * l) * 16384, lane, g_rt, g_cg);
            cstore(c, xl_s, g_rt, g_cg, lane);

            cinit(c, br + l * DD, g_cg, lane);
            gemm_ld(c, af_s, g_Bpack + (2 * l + 1) * 16384, lane, g_rt, g_cg);
            __syncthreads();                     // all warps done reading A-frags
            cstore(c, xr_s, g_rt, g_cg, lane);   // overwrites af region
        }
        __syncthreads();                         // publish xl, xr

        // ==== fused edge phase: alpha + ONLINE softmax + aggregate + LN ====
        // warp w owns nodes {w, w+16, ...}; single pass over incoming edges.
        {
            const float4 We4  = *(const float4*)(We  + l * DD + lane * 4);
            const float4 att4 = *(const float4*)(att + l * DD + lane * 4);
            const float4 cb4  = *(const float4*)(conv_bias + l * DD + lane * 4);
            const float4 lg4  = *(const float4*)(ln_g + l * DD + lane * 4);
            const float4 lb4  = *(const float4*)(ln_b + l * DD + lane * 4);
            for (int n = w; n < NN; n += NW) {
                const float4 xr4 = *(const float4*)(xr_s + n * DD + lane * 4);
                const int e0 = g_off[n], e1 = g_off[n + 1];
                float m = -INFINITY, s = 0.f;
                float v0 = 0.f, v1 = 0.f, v2 = 0.f, v3 = 0.f;
#pragma unroll 2
                for (int i = e0; i < e1; ++i) {
                    const int sidx = esrc_s[i];
                    const float eav = g_eap[i];
                    const float4 xl4 = *(const float4*)(xl_s + sidx * DD + lane * 4);
                    float z0 = xl4.x + xr4.x + eav * We4.x;
                    float z1 = xl4.y + xr4.y + eav * We4.y;
                    float z2 = xl4.z + xr4.z + eav * We4.z;
                    float z3 = xl4.w + xr4.w + eav * We4.w;
                    z0 = z0 > 0.f ? z0 : 0.2f * z0;
                    z1 = z1 > 0.f ? z1 : 0.2f * z1;
                    z2 = z2 > 0.f ? z2 : 0.2f * z2;
                    z3 = z3 > 0.f ? z3 : 0.2f * z3;
                    float p = z0 * att4.x + z1 * att4.y + z2 * att4.z + z3 * att4.w;
                    p += __shfl_xor_sync(0xffffffffu, p, 1);
                    p += __shfl_xor_sync(0xffffffffu, p, 2);
                    p += __shfl_xor_sync(0xffffffffu, p, 4);
                    // p = alpha[e, head] in all 8 lanes of the head group
                    const float mn = fmaxf(m, p);
                    const float cm = __expf(m - mn);   // first iter: exp(-inf)=0
                    const float cp = __expf(p - mn);
                    s  = s * cm + cp;
                    v0 = v0 * cm + cp * xl4.x;
                    v1 = v1 * cm + cp * xl4.y;
                    v2 = v2 * cm + cp * xl4.z;
                    v3 = v3 * cm + cp * xl4.w;
                    m = mn;
                }
                if (e1 > e0) {
                    const float inv = 1.f / s;
                    v0 *= inv; v1 *= inv; v2 *= inv; v3 *= inv;
                }
                v0 += cb4.x; v1 += cb4.y; v2 += cb4.z; v3 += cb4.w;
                float sum = v0 + v1 + v2 + v3;
                float sq  = v0*v0 + v1*v1 + v2*v2 + v3*v3;
#pragma unroll
                for (int o = 16; o; o >>= 1) {
                    sum += __shfl_xor_sync(0xffffffffu, sum, o);
                    sq  += __shfl_xor_sync(0xffffffffu, sq, o);
                }
                const float mu = sum * (1.f / DD);
                const float var = sq * (1.f / DD) - mu * mu;
                const float rstd = rsqrtf(var + 1e-5f);
                float t0v = (v0 - mu) * rstd * lg4.x + lb4.x;
                float t1v = (v1 - mu) * rstd * lg4.y + lb4.y;
                float t2v = (v2 - mu) * rstd * lg4.z + lb4.z;
                float t3v = (v3 - mu) * rstd * lg4.w + lb4.w;
                t0v = t0v > 0.f ? t0v : expm1f(t0v);
                t1v = t1v > 0.f ? t1v : expm1f(t1v);
                t2v = t2v > 0.f ? t2v : expm1f(t2v);
                t3v = t3v > 0.f ? t3v : expm1f(t3v);
                float4 hv = *(const float4*)(h_s + n * DD + lane * 4);
                hv.x += t0v; hv.y += t1v; hv.z += t2v; hv.w += t3v;
                *(float4*)(h_s + n * DD + lane * 4) = hv;
            }
        }
        __syncthreads();                   // publish h before next convert
    }

    // ---- MLP: q = relu([T0, h] @ W1 + b1) -> xl_s  (two K=128 passes) ----
    {
        float c[4][4];
        cinit(c, b1, g_cg, lane);
        convert_T0(x, attr_emb, opt_emb, prior, b, af_s, tid);
        __syncthreads();
        gemm_ld(c, af_s, g_Bpack + 4 * 16384, lane, g_rt, g_cg);
        __syncthreads();                   // all warps done with T0 frags
        convert_A(h_s, af_s, tid);
        __syncthreads();
        gemm_ld(c, af_s, g_Bpack + 5 * 16384, lane, g_rt, g_cg);
        cstore_relu(c, xl_s, g_rt, g_cg, lane);
    }
    __syncthreads();

    float* rel_s = ep_s;          // [0..63], relsum at [64], partials at [128..640)

    // ---- rel[n] = sigmoid(q[n].W2 + b2)   (warp per node) ----
    {
        const long long OR = (long long)NB * DD;
        const float4 w24 = *(const float4*)(W2 + lane * 4);
        for (int n = w; n < NN; n += NW) {
            const float4 qv = *(const float4*)(xl_s + n * DD + lane * 4);
            float p = qv.x * w24.x + qv.y * w24.y + qv.z * w24.z + qv.w * w24.w;
#pragma unroll
            for (int o = 16; o; o >>= 1) p += __shfl_xor_sync(0xffffffffu, p, o);
            if (lane == 0) {
                const float r = 1.f / (1.f + expf(-(p + b2[0])));
                rel_s[n] = r;
                out[OR + (long long)b * NN + n] = r;
            }
        }
    }
    __syncthreads();

    // ---- rel sum (warp 0) ----
    if (w == 0) {
        float v = rel_s[lane] + rel_s[lane + 32];
#pragma unroll
        for (int o = 16; o; o >>= 1) v += __shfl_xor_sync(0xffffffffu, v, o);
        if (lane == 0) rel_s[64] = v;
    }

    // ---- f_scale partials (4-way) ----
    {
        const int d = tid & 127;
        const int q = tid >> 7;            // 0..3
        float acc = 0.f;
        for (int n = q; n < NN; n += 4)
            acc = fmaf(h_s[n * DD + d], rel_s[n], acc);
        ep_s[128 + q * DD + d] = acc;
    }

    // ---- hat_T output: [T0 (recomputed), h]  (float4) ----
    {
        const long long OH = (long long)NB * DD + (long long)NB * NN;
        for (int idx = tid; idx < NN * DD / 4; idx += NT) {
            const int n = idx >> 5, d4 = (idx & 31) * 4;
            const int xv = x[b * NN + n];
            const float pr = prior[n];
            const float4 a4 = *(const float4*)(attr_emb + n * DD + d4);
            const float4 o4 = *(const float4*)(opt_emb + (n * KK + xv) * DD + d4);
            float4 t4;
            t4.x = (a4.x + o4.x) * pr;
            t4.y = (a4.y + o4.y) * pr;
            t4.z = (a4.z + o4.z) * pr;
            t4.w = (a4.w + o4.w) * pr;
            const long long base = OH + ((long long)b * NN + n) * (2 * DD);
            *(float4*)(out + base + d4) = t4;
            *(float4*)(out + base + DD + d4) = *(const float4*)(h_s + n * DD + d4);
        }
    }
    __syncthreads();

    if (tid < DD) {
        const float num = ep_s[128 + tid] + ep_s[256 + tid] +
                          ep_s[384 + tid] + ep_s[512 + tid];
        out[(long long)b * DD + tid] = num / (rel_s[64] + 1e-8f);
    }
}

extern "C" void kernel_launch(void* const* d_in, const int* in_sizes, int n_in,
                              void* d_out, int out_size) {
    const int*   x         = (const int*)d_in[0];
    const int*   ei        = (const int*)d_in[1];
    const float* ea        = (const float*)d_in[2];
    const float* attr_emb  = (const float*)d_in[3];
    const float* opt_emb   = (const float*)d_in[4];
    const float* prior     = (const float*)d_in[5];
    const float* Wl        = (const float*)d_in[6];
    const float* bl        = (const float*)d_in[7];
    const float* Wr        = (const float*)d_in[8];
    const float* br        = (const float*)d_in[9];
    const float* We        = (const float*)d_in[10];
    const float* att       = (const float*)d_in[11];
    const float* conv_bias = (const float*)d_in[12];
    const float* ln_g      = (const float*)d_in[13];
    const float* ln_b      = (const float*)d_in[14];
    const float* W1        = (const float*)d_in[15];
    const float* b1        = (const float*)d_in[16];
    const float* W2        = (const float*)d_in[17];
    const float* b2        = (const float*)d_in[18];
    float* out = (float*)d_out;

    const size_t smem = (3 * NN * DD + 768) * sizeof(float) + EE;
    cudaFuncSetAttribute(gat_kernel, cudaFuncAttributeMaxDynamicSharedMemorySize, (int)smem);

    setup_kernel<<<7, EE>>>(ei, ea, Wl, Wr, W1);
    gat_kernel<<<NB, NT, smem>>>(x, attr_emb, opt_emb, prior,
                                 bl, br, We, att, conv_bias,
                                 ln_g, ln_b, b1, W2, b2, out);
}